// round 1
// baseline (speedup 1.0000x reference)
#include <cuda_runtime.h>
#include <math.h>

#define BATCH 4
#define DIMC  384
#define NTOK  2304      // 48*48
#define NHEAD 8
#define DEPTH 48
#define QKVD  1152
#define LN_EPS 1e-5f

// Scratch (no allocations allowed)
__device__ float g_xn  [BATCH*NTOK*DIMC];          // layernormed x, [B*N, C]
__device__ float g_q   [BATCH*NHEAD*NTOK*DEPTH];   // [B,H,N,d]
__device__ float g_k   [BATCH*NHEAD*NTOK*DEPTH];
__device__ float g_v   [BATCH*NHEAD*NTOK*DEPTH];
__device__ float g_attn[BATCH*NTOK*DIMC];          // attention out, [B*N, C]

__inline__ __device__ float warpsum(float v) {
    #pragma unroll
    for (int o = 16; o > 0; o >>= 1) v += __shfl_down_sync(0xffffffffu, v, o);
    return v;
}

// ---------------------------------------------------------------------------
// 1) LayerNorm + implicit NCHW->NLC transpose.
//    One block per token (b,n); 384 threads, one per channel.
// ---------------------------------------------------------------------------
__global__ void ln_kernel(const float* __restrict__ feat,
                          const float* __restrict__ gamma,
                          const float* __restrict__ beta) {
    int bn = blockIdx.x;                 // 0..9215
    int b  = bn / NTOK, n = bn % NTOK;
    int c  = threadIdx.x;                // 0..383
    float v = feat[(b*DIMC + c)*NTOK + n];

    float s  = warpsum(v);
    float s2 = warpsum(v*v);
    __shared__ float ws[12], ws2[12];
    __shared__ float mean_s, rstd_s;
    int warp = c >> 5, lane = c & 31;
    if (lane == 0) { ws[warp] = s; ws2[warp] = s2; }
    __syncthreads();
    if (c < 32) {
        float t  = (c < 12) ? ws[c]  : 0.f;
        float t2 = (c < 12) ? ws2[c] : 0.f;
        t = warpsum(t); t2 = warpsum(t2);
        if (c == 0) {
            float mu  = t * (1.f/DIMC);
            float var = t2 * (1.f/DIMC) - mu*mu;
            mean_s = mu;
            rstd_s = rsqrtf(var + LN_EPS);
        }
    }
    __syncthreads();
    g_xn[bn*DIMC + c] = (v - mean_s) * rstd_s * gamma[c] + beta[c];
}

// ---------------------------------------------------------------------------
// 2) QKV GEMM: C[m,d] = sum_k xn[m,k] * Wqkv[d,k], scatter into q/k/v [B,H,N,d]
//    64x64x16 tiles, 256 threads, 4x4 micro-tile.
// ---------------------------------------------------------------------------
__global__ void __launch_bounds__(256) qkv_gemm(const float* __restrict__ W) {
    __shared__ float As[16][64];
    __shared__ float Bs[16][64];
    int m0 = blockIdx.y * 64;
    int d0 = blockIdx.x * 64;
    int t  = threadIdx.x;
    int tx = t & 15, ty = t >> 4;
    int lrow = t >> 2, lkk = (t & 3) << 2;

    float acc[4][4] = {};
    const float* Arow = g_xn + (size_t)(m0 + lrow)*DIMC + lkk;
    const float* Brow = W    + (size_t)(d0 + lrow)*DIMC + lkk;

    for (int k0 = 0; k0 < DIMC; k0 += 16) {
        float4 av = *(const float4*)(Arow + k0);
        float4 bv = *(const float4*)(Brow + k0);
        As[lkk+0][lrow]=av.x; As[lkk+1][lrow]=av.y; As[lkk+2][lrow]=av.z; As[lkk+3][lrow]=av.w;
        Bs[lkk+0][lrow]=bv.x; Bs[lkk+1][lrow]=bv.y; Bs[lkk+2][lrow]=bv.z; Bs[lkk+3][lrow]=bv.w;
        __syncthreads();
        #pragma unroll
        for (int kk = 0; kk < 16; kk++) {
            float4 a  = *(const float4*)&As[kk][ty*4];
            float4 bq = *(const float4*)&Bs[kk][tx*4];
            float ar[4] = {a.x,a.y,a.z,a.w};
            float br[4] = {bq.x,bq.y,bq.z,bq.w};
            #pragma unroll
            for (int i = 0; i < 4; i++)
                #pragma unroll
                for (int j = 0; j < 4; j++) acc[i][j] += ar[i]*br[j];
        }
        __syncthreads();
    }

    #pragma unroll
    for (int i = 0; i < 4; i++) {
        int m = m0 + ty*4 + i;
        int b = m / NTOK, n = m % NTOK;
        #pragma unroll
        for (int j = 0; j < 4; j++) {
            int d = d0 + tx*4 + j;
            int which = d / DIMC;           // constant per tile (384 % 64 == 0)
            int r = d - which*DIMC;
            int h = r / DEPTH, dd = r - h*DEPTH;
            float* dst = (which == 0) ? g_q : (which == 1) ? g_k : g_v;
            dst[((size_t)(b*NHEAD + h)*NTOK + n)*DEPTH + dd] = acc[i][j];
        }
    }
}

// ---------------------------------------------------------------------------
// 3) Flash-style attention. One thread per query, 64 queries / block,
//    K/V tiles of 64 keys in smem, online softmax with conditional rescale.
// ---------------------------------------------------------------------------
__global__ void __launch_bounds__(64) attn_kernel(const float* __restrict__ tau) {
    __shared__ float Ks[64*DEPTH];
    __shared__ float Vs[64*DEPTH];
    int qc = blockIdx.x, h = blockIdx.y, b = blockIdx.z;
    int tid = threadIdx.x;
    int bh = b*NHEAD + h;
    float scale = expf(tau[h]);

    const float* qp = g_q + ((size_t)bh*NTOK + qc*64 + tid)*DEPTH;
    float qreg[DEPTH];
    #pragma unroll
    for (int dd = 0; dd < DEPTH; dd += 4) {
        float4 qq = *(const float4*)(qp + dd);
        qreg[dd] = qq.x; qreg[dd+1] = qq.y; qreg[dd+2] = qq.z; qreg[dd+3] = qq.w;
    }

    float acc[DEPTH] = {};
    float mrun = -1e30f, lrun = 0.f;

    for (int j0 = 0; j0 < NTOK; j0 += 64) {
        const float4* kb = (const float4*)(g_k + ((size_t)bh*NTOK + j0)*DEPTH);
        const float4* vb = (const float4*)(g_v + ((size_t)bh*NTOK + j0)*DEPTH);
        float4* K4 = (float4*)Ks; float4* V4 = (float4*)Vs;
        #pragma unroll 4
        for (int i = tid; i < 64*DEPTH/4; i += 64) { K4[i] = kb[i]; V4[i] = vb[i]; }
        __syncthreads();

        for (int j = 0; j < 64; j++) {
            const float* kr = Ks + j*DEPTH;
            float s0=0.f, s1=0.f, s2=0.f, s3=0.f;
            #pragma unroll
            for (int dd = 0; dd < DEPTH; dd += 4) {
                s0 += qreg[dd+0]*kr[dd+0];
                s1 += qreg[dd+1]*kr[dd+1];
                s2 += qreg[dd+2]*kr[dd+2];
                s3 += qreg[dd+3]*kr[dd+3];
            }
            float s = ((s0+s1)+(s2+s3)) * scale;
            if (s > mrun) {                 // rare after warm-up: ~O(ln N) times
                float corr = __expf(mrun - s);
                lrun *= corr;
                #pragma unroll
                for (int dd = 0; dd < DEPTH; dd++) acc[dd] *= corr;
                mrun = s;
            }
            float p = __expf(s - mrun);
            lrun += p;
            const float* vr = Vs + j*DEPTH;
            #pragma unroll
            for (int dd = 0; dd < DEPTH; dd++) acc[dd] += p * vr[dd];
        }
        __syncthreads();
    }

    float inv = 1.f / lrun;
    float* op = g_attn + ((size_t)(b*NTOK + qc*64 + tid))*DIMC + h*DEPTH;
    #pragma unroll
    for (int dd = 0; dd < DEPTH; dd += 4) {
        float4 o; o.x = acc[dd]*inv; o.y = acc[dd+1]*inv;
        o.z = acc[dd+2]*inv; o.w = acc[dd+3]*inv;
        *(float4*)(op + dd) = o;
    }
}

// ---------------------------------------------------------------------------
// 4) Output projection + bias + transpose back to [B, C, H*W].
// ---------------------------------------------------------------------------
__global__ void __launch_bounds__(256) out_gemm(const float* __restrict__ W,
                                                const float* __restrict__ bias,
                                                float* __restrict__ out) {
    __shared__ float As[16][64];
    __shared__ float Bs[16][64];
    int m0 = blockIdx.y * 64;
    int d0 = blockIdx.x * 64;
    int t  = threadIdx.x;
    int tx = t & 15, ty = t >> 4;
    int lrow = t >> 2, lkk = (t & 3) << 2;

    float acc[4][4] = {};
    const float* Arow = g_attn + (size_t)(m0 + lrow)*DIMC + lkk;
    const float* Brow = W      + (size_t)(d0 + lrow)*DIMC + lkk;

    for (int k0 = 0; k0 < DIMC; k0 += 16) {
        float4 av = *(const float4*)(Arow + k0);
        float4 bv = *(const float4*)(Brow + k0);
        As[lkk+0][lrow]=av.x; As[lkk+1][lrow]=av.y; As[lkk+2][lrow]=av.z; As[lkk+3][lrow]=av.w;
        Bs[lkk+0][lrow]=bv.x; Bs[lkk+1][lrow]=bv.y; Bs[lkk+2][lrow]=bv.z; Bs[lkk+3][lrow]=bv.w;
        __syncthreads();
        #pragma unroll
        for (int kk = 0; kk < 16; kk++) {
            float4 a  = *(const float4*)&As[kk][ty*4];
            float4 bq = *(const float4*)&Bs[kk][tx*4];
            float ar[4] = {a.x,a.y,a.z,a.w};
            float br[4] = {bq.x,bq.y,bq.z,bq.w};
            #pragma unroll
            for (int i = 0; i < 4; i++)
                #pragma unroll
                for (int j = 0; j < 4; j++) acc[i][j] += ar[i]*br[j];
        }
        __syncthreads();
    }

    #pragma unroll
    for (int i = 0; i < 4; i++) {
        int m = m0 + ty*4 + i;
        int b = m / NTOK, n = m % NTOK;
        #pragma unroll
        for (int j = 0; j < 4; j++) {
            int d = d0 + tx*4 + j;
            out[(size_t)(b*DIMC + d)*NTOK + n] = acc[i][j] + bias[d];
        }
    }
}

// ---------------------------------------------------------------------------
extern "C" void kernel_launch(void* const* d_in, const int* in_sizes, int n_in,
                              void* d_out, int out_size) {
    const float* feat  = (const float*)d_in[0];
    const float* gamma = (const float*)d_in[1];
    const float* beta  = (const float*)d_in[2];
    const float* tau   = (const float*)d_in[3];
    const float* w_qkv = (const float*)d_in[4];
    const float* w_out = (const float*)d_in[5];
    const float* b_out = (const float*)d_in[6];
    float* out = (float*)d_out;

    ln_kernel<<<BATCH*NTOK, DIMC>>>(feat, gamma, beta);
    qkv_gemm<<<dim3(QKVD/64, BATCH*NTOK/64), 256>>>(w_qkv);
    attn_kernel<<<dim3(NTOK/64, NHEAD, BATCH), 64>>>(tau);
    out_gemm<<<dim3(DIMC/64, BATCH*NTOK/64), 256>>>(w_out, b_out, out);
}

// round 2
// speedup vs baseline: 2.0287x; 2.0287x over previous
#include <cuda_runtime.h>
#include <cuda_bf16.h>
#include <math.h>

#define BATCH 4
#define DIMC  384
#define NTOK  2304      // 48*48
#define NHEAD 8
#define DEPTH 48
#define QKVD  1152
#define LN_EPS 1e-5f
#define BH    (BATCH*NHEAD)

// Scratch (no allocations allowed)
__device__ float g_xn  [BATCH*NTOK*DIMC];          // layernormed x, [B*N, C]
__device__ float g_attn[BATCH*NTOK*DIMC];          // attention out, [B*N, C]
// bf16 split operands for tensor-core attention
__device__ __nv_bfloat16 g_qhi[BH*NTOK*DEPTH], g_qlo[BH*NTOK*DEPTH];   // [bh, n, d]
__device__ __nv_bfloat16 g_khi[BH*NTOK*DEPTH], g_klo[BH*NTOK*DEPTH];   // [bh, n, d]
__device__ __nv_bfloat16 g_vthi[BH*DEPTH*NTOK], g_vtlo[BH*DEPTH*NTOK]; // [bh, d, n] (transposed!)

__inline__ __device__ float warpsum(float v) {
    #pragma unroll
    for (int o = 16; o > 0; o >>= 1) v += __shfl_down_sync(0xffffffffu, v, o);
    return v;
}

__device__ __forceinline__ void mma16816(float* d, const unsigned* a, unsigned b0, unsigned b1) {
    asm volatile(
        "mma.sync.aligned.m16n8k16.row.col.f32.bf16.bf16.f32 "
        "{%0,%1,%2,%3},{%4,%5,%6,%7},{%8,%9},{%0,%1,%2,%3};"
        : "+f"(d[0]), "+f"(d[1]), "+f"(d[2]), "+f"(d[3])
        : "r"(a[0]), "r"(a[1]), "r"(a[2]), "r"(a[3]), "r"(b0), "r"(b1));
}

// ---------------------------------------------------------------------------
// 1) LayerNorm + implicit NCHW->NLC transpose.
// ---------------------------------------------------------------------------
__global__ void ln_kernel(const float* __restrict__ feat,
                          const float* __restrict__ gamma,
                          const float* __restrict__ beta) {
    int bn = blockIdx.x;
    int b  = bn / NTOK, n = bn % NTOK;
    int c  = threadIdx.x;
    float v = feat[(b*DIMC + c)*NTOK + n];

    float s  = warpsum(v);
    float s2 = warpsum(v*v);
    __shared__ float ws[12], ws2[12];
    __shared__ float mean_s, rstd_s;
    int warp = c >> 5, lane = c & 31;
    if (lane == 0) { ws[warp] = s; ws2[warp] = s2; }
    __syncthreads();
    if (c < 32) {
        float t  = (c < 12) ? ws[c]  : 0.f;
        float t2 = (c < 12) ? ws2[c] : 0.f;
        t = warpsum(t); t2 = warpsum(t2);
        if (c == 0) {
            float mu  = t * (1.f/DIMC);
            float var = t2 * (1.f/DIMC) - mu*mu;
            mean_s = mu;
            rstd_s = rsqrtf(var + LN_EPS);
        }
    }
    __syncthreads();
    g_xn[bn*DIMC + c] = (v - mean_s) * rstd_s * gamma[c] + beta[c];
}

// ---------------------------------------------------------------------------
// 2) QKV GEMM (SIMT fp32). Epilogue splits to bf16 hi/lo; V stored transposed.
// ---------------------------------------------------------------------------
__global__ void __launch_bounds__(256) qkv_gemm(const float* __restrict__ W) {
    __shared__ float As[16][64];
    __shared__ float Bs[16][64];
    int m0 = blockIdx.y * 64;
    int d0 = blockIdx.x * 64;
    int t  = threadIdx.x;
    int tx = t & 15, ty = t >> 4;
    int lrow = t >> 2, lkk = (t & 3) << 2;

    float acc[4][4] = {};
    const float* Arow = g_xn + (size_t)(m0 + lrow)*DIMC + lkk;
    const float* Brow = W    + (size_t)(d0 + lrow)*DIMC + lkk;

    for (int k0 = 0; k0 < DIMC; k0 += 16) {
        float4 av = *(const float4*)(Arow + k0);
        float4 bv = *(const float4*)(Brow + k0);
        As[lkk+0][lrow]=av.x; As[lkk+1][lrow]=av.y; As[lkk+2][lrow]=av.z; As[lkk+3][lrow]=av.w;
        Bs[lkk+0][lrow]=bv.x; Bs[lkk+1][lrow]=bv.y; Bs[lkk+2][lrow]=bv.z; Bs[lkk+3][lrow]=bv.w;
        __syncthreads();
        #pragma unroll
        for (int kk = 0; kk < 16; kk++) {
            float4 a  = *(const float4*)&As[kk][ty*4];
            float4 bq = *(const float4*)&Bs[kk][tx*4];
            float ar[4] = {a.x,a.y,a.z,a.w};
            float br[4] = {bq.x,bq.y,bq.z,bq.w};
            #pragma unroll
            for (int i = 0; i < 4; i++)
                #pragma unroll
                for (int j = 0; j < 4; j++) acc[i][j] += ar[i]*br[j];
        }
        __syncthreads();
    }

    int which = d0 / DIMC;   // 0=q, 1=k, 2=v (constant per block: 384 % 64 == 0)
    #pragma unroll
    for (int i = 0; i < 4; i++) {
        int m = m0 + ty*4 + i;
        int b = m / NTOK, n = m % NTOK;
        #pragma unroll
        for (int j = 0; j < 4; j++) {
            int d = d0 + tx*4 + j;
            int r = d - which*DIMC;
            int h = r / DEPTH, dd = r - h*DEPTH;
            int bh = b*NHEAD + h;
            float x = acc[i][j];
            __nv_bfloat16 hi = __float2bfloat16_rn(x);
            __nv_bfloat16 lo = __float2bfloat16_rn(x - __bfloat162float(hi));
            if (which == 0) {
                size_t idx = ((size_t)bh*NTOK + n)*DEPTH + dd;
                g_qhi[idx] = hi; g_qlo[idx] = lo;
            } else if (which == 1) {
                size_t idx = ((size_t)bh*NTOK + n)*DEPTH + dd;
                g_khi[idx] = hi; g_klo[idx] = lo;
            } else {
                size_t idx = ((size_t)bh*DEPTH + dd)*NTOK + n;
                g_vthi[idx] = hi; g_vtlo[idx] = lo;
            }
        }
    }
}

// ---------------------------------------------------------------------------
// 3) Tensor-core flash attention (bf16 split: hi*hi + hi*lo + lo*hi).
//    Block = 128 threads (4 warps), 64 queries per block (16 per warp),
//    key tiles of 64 staged in smem. m16n8k16 bf16 mma throughout.
// ---------------------------------------------------------------------------
__global__ void __launch_bounds__(128) attn_mma(const float* __restrict__ tau) {
    __shared__ __nv_bfloat16 Khs[64][56];   // pad 48->56: conflict-free B-frag LDS
    __shared__ __nv_bfloat16 Kls[64][56];
    __shared__ __nv_bfloat16 Vhs[48][72];   // V^T tile, pad 64->72
    __shared__ __nv_bfloat16 Vls[48][72];

    int qc = blockIdx.x, h = blockIdx.y, b = blockIdx.z;
    int bh = b*NHEAD + h;
    int tid = threadIdx.x, w = tid >> 5, lane = tid & 31;
    int g = lane >> 2, tig = lane & 3;
    float scale2 = expf(tau[h]) * 1.44269504088896f;   // log2(e): softmax in base 2
    int m0 = qc*64 + w*16;

    // ---- Q fragments (persistent), hi and lo, 3 k-steps of 16 over DEPTH=48
    const __nv_bfloat16* qh = g_qhi + (size_t)bh*NTOK*DEPTH;
    const __nv_bfloat16* ql = g_qlo + (size_t)bh*NTOK*DEPTH;
    unsigned aqh[3][4], aql[3][4];
    #pragma unroll
    for (int ks = 0; ks < 3; ks++) {
        int c0 = ks*16 + 2*tig;
        aqh[ks][0] = *(const unsigned*)(qh + (size_t)(m0+g  )*DEPTH + c0);
        aqh[ks][1] = *(const unsigned*)(qh + (size_t)(m0+g+8)*DEPTH + c0);
        aqh[ks][2] = *(const unsigned*)(qh + (size_t)(m0+g  )*DEPTH + c0 + 8);
        aqh[ks][3] = *(const unsigned*)(qh + (size_t)(m0+g+8)*DEPTH + c0 + 8);
        aql[ks][0] = *(const unsigned*)(ql + (size_t)(m0+g  )*DEPTH + c0);
        aql[ks][1] = *(const unsigned*)(ql + (size_t)(m0+g+8)*DEPTH + c0);
        aql[ks][2] = *(const unsigned*)(ql + (size_t)(m0+g  )*DEPTH + c0 + 8);
        aql[ks][3] = *(const unsigned*)(ql + (size_t)(m0+g+8)*DEPTH + c0 + 8);
    }

    float o[6][4] = {};                       // PV accum: 16 x 48 per warp
    float mr[2] = {-1e30f, -1e30f};           // running row max (base-2 domain)
    float lp[2] = {0.f, 0.f};                 // per-lane partial softmax denominators

    const unsigned* Kgh = (const unsigned*)(g_khi + (size_t)bh*NTOK*DEPTH);
    const unsigned* Kgl = (const unsigned*)(g_klo + (size_t)bh*NTOK*DEPTH);

    for (int j0 = 0; j0 < NTOK; j0 += 64) {
        // ---- stage K (hi/lo) and V^T (hi/lo) tiles
        __syncthreads();
        #pragma unroll 4
        for (int idx = tid; idx < 64*24; idx += 128) {
            int row = idx / 24, c = idx % 24;
            ((unsigned*)Khs)[row*28 + c] = Kgh[(size_t)(j0+row)*24 + c];
            ((unsigned*)Kls)[row*28 + c] = Kgl[(size_t)(j0+row)*24 + c];
        }
        #pragma unroll 4
        for (int idx = tid; idx < 48*32; idx += 128) {
            int dd = idx / 32, c = idx % 32;
            const unsigned* vh = (const unsigned*)(g_vthi + ((size_t)bh*DEPTH+dd)*NTOK + j0);
            const unsigned* vl = (const unsigned*)(g_vtlo + ((size_t)bh*DEPTH+dd)*NTOK + j0);
            ((unsigned*)Vhs)[dd*36 + c] = vh[c];
            ((unsigned*)Vls)[dd*36 + c] = vl[c];
        }
        __syncthreads();

        // ---- S = Q K^T (3-term split), 8 n-tiles of 8 keys
        float s[8][4];
        #pragma unroll
        for (int nt = 0; nt < 8; nt++) { s[nt][0]=0.f; s[nt][1]=0.f; s[nt][2]=0.f; s[nt][3]=0.f; }
        #pragma unroll
        for (int nt = 0; nt < 8; nt++) {
            const __nv_bfloat16* krh = &Khs[nt*8 + g][0];
            const __nv_bfloat16* krl = &Kls[nt*8 + g][0];
            #pragma unroll
            for (int ks = 0; ks < 3; ks++) {
                unsigned bh0 = *(const unsigned*)(krh + ks*16 + 2*tig);
                unsigned bh1 = *(const unsigned*)(krh + ks*16 + 2*tig + 8);
                unsigned bl0 = *(const unsigned*)(krl + ks*16 + 2*tig);
                unsigned bl1 = *(const unsigned*)(krl + ks*16 + 2*tig + 8);
                mma16816(s[nt], aqh[ks], bh0, bh1);   // hi*hi
                mma16816(s[nt], aqh[ks], bl0, bl1);   // hi*lo
                mma16816(s[nt], aql[ks], bh0, bh1);   // lo*hi
            }
        }

        // ---- online softmax (rows g and g+8); lanes with same g share a row
        float mx0 = -1e30f, mx1 = -1e30f;
        #pragma unroll
        for (int nt = 0; nt < 8; nt++) {
            s[nt][0] *= scale2; s[nt][1] *= scale2; s[nt][2] *= scale2; s[nt][3] *= scale2;
            mx0 = fmaxf(mx0, fmaxf(s[nt][0], s[nt][1]));
            mx1 = fmaxf(mx1, fmaxf(s[nt][2], s[nt][3]));
        }
        #pragma unroll
        for (int off = 1; off <= 2; off <<= 1) {
            mx0 = fmaxf(mx0, __shfl_xor_sync(0xffffffffu, mx0, off));
            mx1 = fmaxf(mx1, __shfl_xor_sync(0xffffffffu, mx1, off));
        }
        float mn0 = fmaxf(mr[0], mx0), mn1 = fmaxf(mr[1], mx1);
        float cr0 = exp2f(mr[0] - mn0), cr1 = exp2f(mr[1] - mn1);
        mr[0] = mn0; mr[1] = mn1;
        lp[0] *= cr0; lp[1] *= cr1;
        #pragma unroll
        for (int nt2 = 0; nt2 < 6; nt2++) {
            o[nt2][0] *= cr0; o[nt2][1] *= cr0;
            o[nt2][2] *= cr1; o[nt2][3] *= cr1;
        }

        // ---- P = exp2(s - m), split to bf16 hi/lo, packed as A fragments
        unsigned Ph0[8], Ph1[8], Pl0[8], Pl1[8];
        #pragma unroll
        for (int nt = 0; nt < 8; nt++) {
            float p0 = exp2f(s[nt][0] - mr[0]);
            float p1 = exp2f(s[nt][1] - mr[0]);
            float p2 = exp2f(s[nt][2] - mr[1]);
            float p3 = exp2f(s[nt][3] - mr[1]);
            lp[0] += p0 + p1; lp[1] += p2 + p3;
            __nv_bfloat16 h0 = __float2bfloat16_rn(p0), h1 = __float2bfloat16_rn(p1);
            __nv_bfloat16 h2 = __float2bfloat16_rn(p2), h3 = __float2bfloat16_rn(p3);
            __nv_bfloat16 l0 = __float2bfloat16_rn(p0 - __bfloat162float(h0));
            __nv_bfloat16 l1 = __float2bfloat16_rn(p1 - __bfloat162float(h1));
            __nv_bfloat16 l2 = __float2bfloat16_rn(p2 - __bfloat162float(h2));
            __nv_bfloat16 l3 = __float2bfloat16_rn(p3 - __bfloat162float(h3));
            __nv_bfloat162 t;
            t = __halves2bfloat162(h0, h1); Ph0[nt] = *(unsigned*)&t;
            t = __halves2bfloat162(h2, h3); Ph1[nt] = *(unsigned*)&t;
            t = __halves2bfloat162(l0, l1); Pl0[nt] = *(unsigned*)&t;
            t = __halves2bfloat162(l2, l3); Pl1[nt] = *(unsigned*)&t;
        }

        // ---- O += P V (3-term split); k = 64 keys (4 steps), n = 48 (6 tiles)
        #pragma unroll
        for (int nt2 = 0; nt2 < 6; nt2++) {
            const __nv_bfloat16* vrh = &Vhs[nt2*8 + g][0];
            const __nv_bfloat16* vrl = &Vls[nt2*8 + g][0];
            #pragma unroll
            for (int ksj = 0; ksj < 4; ksj++) {
                unsigned bh0 = *(const unsigned*)(vrh + ksj*16 + 2*tig);
                unsigned bh1 = *(const unsigned*)(vrh + ksj*16 + 2*tig + 8);
                unsigned bl0 = *(const unsigned*)(vrl + ksj*16 + 2*tig);
                unsigned bl1 = *(const unsigned*)(vrl + ksj*16 + 2*tig + 8);
                unsigned Ahi[4] = {Ph0[2*ksj], Ph1[2*ksj], Ph0[2*ksj+1], Ph1[2*ksj+1]};
                unsigned Alo[4] = {Pl0[2*ksj], Pl1[2*ksj], Pl0[2*ksj+1], Pl1[2*ksj+1]};
                mma16816(o[nt2], Ahi, bh0, bh1);   // Phi*Vhi
                mma16816(o[nt2], Ahi, bl0, bl1);   // Phi*Vlo
                mma16816(o[nt2], Alo, bh0, bh1);   // Plo*Vhi
            }
        }
    }

    // ---- finalize: reduce l across the 4 lanes of each row group, write out
    #pragma unroll
    for (int off = 1; off <= 2; off <<= 1) {
        lp[0] += __shfl_xor_sync(0xffffffffu, lp[0], off);
        lp[1] += __shfl_xor_sync(0xffffffffu, lp[1], off);
    }
    float inv0 = 1.f / lp[0], inv1 = 1.f / lp[1];
    float* out0 = g_attn + ((size_t)(b*NTOK + m0 + g    ))*DIMC + h*DEPTH;
    float* out1 = g_attn + ((size_t)(b*NTOK + m0 + g + 8))*DIMC + h*DEPTH;
    #pragma unroll
    for (int nt2 = 0; nt2 < 6; nt2++) {
        float2 r0 = make_float2(o[nt2][0]*inv0, o[nt2][1]*inv0);
        float2 r1 = make_float2(o[nt2][2]*inv1, o[nt2][3]*inv1);
        *(float2*)(out0 + nt2*8 + 2*tig) = r0;
        *(float2*)(out1 + nt2*8 + 2*tig) = r1;
    }
}

// ---------------------------------------------------------------------------
// 4) Output projection + bias + transpose back to [B, C, H*W].
// ---------------------------------------------------------------------------
__global__ void __launch_bounds__(256) out_gemm(const float* __restrict__ W,
                                                const float* __restrict__ bias,
                                                float* __restrict__ out) {
    __shared__ float As[16][64];
    __shared__ float Bs[16][64];
    int m0 = blockIdx.y * 64;
    int d0 = blockIdx.x * 64;
    int t  = threadIdx.x;
    int tx = t & 15, ty = t >> 4;
    int lrow = t >> 2, lkk = (t & 3) << 2;

    float acc[4][4] = {};
    const float* Arow = g_attn + (size_t)(m0 + lrow)*DIMC + lkk;
    const float* Brow = W      + (size_t)(d0 + lrow)*DIMC + lkk;

    for (int k0 = 0; k0 < DIMC; k0 += 16) {
        float4 av = *(const float4*)(Arow + k0);
        float4 bv = *(const float4*)(Brow + k0);
        As[lkk+0][lrow]=av.x; As[lkk+1][lrow]=av.y; As[lkk+2][lrow]=av.z; As[lkk+3][lrow]=av.w;
        Bs[lkk+0][lrow]=bv.x; Bs[lkk+1][lrow]=bv.y; Bs[lkk+2][lrow]=bv.z; Bs[lkk+3][lrow]=bv.w;
        __syncthreads();
        #pragma unroll
        for (int kk = 0; kk < 16; kk++) {
            float4 a  = *(const float4*)&As[kk][ty*4];
            float4 bq = *(const float4*)&Bs[kk][tx*4];
            float ar[4] = {a.x,a.y,a.z,a.w};
            float br[4] = {bq.x,bq.y,bq.z,bq.w};
            #pragma unroll
            for (int i = 0; i < 4; i++)
                #pragma unroll
                for (int j = 0; j < 4; j++) acc[i][j] += ar[i]*br[j];
        }
        __syncthreads();
    }

    #pragma unroll
    for (int i = 0; i < 4; i++) {
        int m = m0 + ty*4 + i;
        int b = m / NTOK, n = m % NTOK;
        #pragma unroll
        for (int j = 0; j < 4; j++) {
            int d = d0 + tx*4 + j;
            out[(size_t)(b*DIMC + d)*NTOK + n] = acc[i][j] + bias[d];
        }
    }
}

// ---------------------------------------------------------------------------
extern "C" void kernel_launch(void* const* d_in, const int* in_sizes, int n_in,
                              void* d_out, int out_size) {
    const float* feat  = (const float*)d_in[0];
    const float* gamma = (const float*)d_in[1];
    const float* beta  = (const float*)d_in[2];
    const float* tau   = (const float*)d_in[3];
    const float* w_qkv = (const float*)d_in[4];
    const float* w_out = (const float*)d_in[5];
    const float* b_out = (const float*)d_in[6];
    float* out = (float*)d_out;

    ln_kernel<<<BATCH*NTOK, DIMC>>>(feat, gamma, beta);
    qkv_gemm<<<dim3(QKVD/64, BATCH*NTOK/64), 256>>>(w_qkv);
    attn_mma<<<dim3(NTOK/64, NHEAD, BATCH), 128>>>(tau);
    out_gemm<<<dim3(DIMC/64, BATCH*NTOK/64), 256>>>(w_out, b_out, out);
}

// round 3
// speedup vs baseline: 3.1077x; 1.5318x over previous
#include <cuda_runtime.h>
#include <cuda_bf16.h>
#include <math.h>

#define BATCH 4
#define DIMC  384
#define NTOK  2304      // 48*48
#define NHEAD 8
#define DEPTH 48
#define QKVD  1152
#define LN_EPS 1e-5f
#define BH    (BATCH*NHEAD)

// ---------------- scratch (no allocations allowed) -------------------------
__device__ __nv_bfloat16 g_xh [BATCH*NTOK*DIMC], g_xl [BATCH*NTOK*DIMC];   // LN out split
__device__ __nv_bfloat16 g_ah [BATCH*NTOK*DIMC], g_al [BATCH*NTOK*DIMC];   // attn out split
__device__ __nv_bfloat16 g_wqh[QKVD*DIMC],       g_wql[QKVD*DIMC];
__device__ __nv_bfloat16 g_woh[DIMC*DIMC],       g_wol[DIMC*DIMC];
__device__ __nv_bfloat16 g_qhi[BH*NTOK*DEPTH], g_qlo[BH*NTOK*DEPTH];   // [bh,n,d]
__device__ __nv_bfloat16 g_khi[BH*NTOK*DEPTH], g_klo[BH*NTOK*DEPTH];   // [bh,n,d]
__device__ __nv_bfloat16 g_vthi[BH*DEPTH*NTOK], g_vtlo[BH*DEPTH*NTOK]; // [bh,d,n]

__inline__ __device__ float warpsum(float v) {
    #pragma unroll
    for (int o = 16; o > 0; o >>= 1) v += __shfl_down_sync(0xffffffffu, v, o);
    return v;
}

__device__ __forceinline__ void mma16816(float* d, const unsigned* a, unsigned b0, unsigned b1) {
    asm volatile(
        "mma.sync.aligned.m16n8k16.row.col.f32.bf16.bf16.f32 "
        "{%0,%1,%2,%3},{%4,%5,%6,%7},{%8,%9},{%0,%1,%2,%3};"
        : "+f"(d[0]), "+f"(d[1]), "+f"(d[2]), "+f"(d[3])
        : "r"(a[0]), "r"(a[1]), "r"(a[2]), "r"(a[3]), "r"(b0), "r"(b1));
}

__device__ __forceinline__ unsigned pack2(__nv_bfloat16 a, __nv_bfloat16 b) {
    __nv_bfloat162 t = __halves2bfloat162(a, b);
    return *(unsigned*)&t;
}

// ---------------------------------------------------------------------------
// 0) split weights into bf16 hi/lo
// ---------------------------------------------------------------------------
__global__ void split_w(const float* __restrict__ wq, const float* __restrict__ wo) {
    int i = blockIdx.x*256 + threadIdx.x;
    if (i < QKVD*DIMC) {
        float x = wq[i];
        __nv_bfloat16 hi = __float2bfloat16_rn(x);
        g_wqh[i] = hi; g_wql[i] = __float2bfloat16_rn(x - __bfloat162float(hi));
    }
    if (i < DIMC*DIMC) {
        float x = wo[i];
        __nv_bfloat16 hi = __float2bfloat16_rn(x);
        g_woh[i] = hi; g_wol[i] = __float2bfloat16_rn(x - __bfloat162float(hi));
    }
}

// ---------------------------------------------------------------------------
// 1) LayerNorm + NCHW->NLC transpose; emits bf16 hi/lo split.
// ---------------------------------------------------------------------------
__global__ void ln_kernel(const float* __restrict__ feat,
                          const float* __restrict__ gamma,
                          const float* __restrict__ beta) {
    int bn = blockIdx.x;
    int b  = bn / NTOK, n = bn % NTOK;
    int c  = threadIdx.x;
    float v = feat[(b*DIMC + c)*NTOK + n];

    float s  = warpsum(v);
    float s2 = warpsum(v*v);
    __shared__ float ws[12], ws2[12];
    __shared__ float mean_s, rstd_s;
    int warp = c >> 5, lane = c & 31;
    if (lane == 0) { ws[warp] = s; ws2[warp] = s2; }
    __syncthreads();
    if (c < 32) {
        float t  = (c < 12) ? ws[c]  : 0.f;
        float t2 = (c < 12) ? ws2[c] : 0.f;
        t = warpsum(t); t2 = warpsum(t2);
        if (c == 0) {
            float mu  = t * (1.f/DIMC);
            float var = t2 * (1.f/DIMC) - mu*mu;
            mean_s = mu;
            rstd_s = rsqrtf(var + LN_EPS);
        }
    }
    __syncthreads();
    float x = (v - mean_s) * rstd_s * gamma[c] + beta[c];
    __nv_bfloat16 hi = __float2bfloat16_rn(x);
    g_xh[bn*DIMC + c] = hi;
    g_xl[bn*DIMC + c] = __float2bfloat16_rn(x - __bfloat162float(hi));
}

// ---------------------------------------------------------------------------
// Tensor-core GEMM mainloop: C[128x64] += A[128x384] * B[64x384]^T
// (A,B bf16 hi/lo split; 3-term mma). 8 warps: 4 along M x 2 along N.
// smem word layout padded 16->20 words/row: conflict-free fragment LDS.
// ---------------------------------------------------------------------------
struct GemmSmem {
    unsigned Ah[128][20], Al[128][20], Bh[64][20], Bl[64][20];
};

__device__ __forceinline__ void gemm_mainloop(
        GemmSmem* sm,
        const unsigned* Agh, const unsigned* Agl,
        const unsigned* Bgh, const unsigned* Bgl,
        int tid, int mw, int nw, int g, int tig,
        float acc[2][4][4]) {
    for (int kc = 0; kc < 192; kc += 16) {        // word (=2 bf16) units
        __syncthreads();
        #pragma unroll 4
        for (int i = tid; i < 128*16; i += 256) {
            int r = i >> 4, c = i & 15;
            sm->Ah[r][c] = Agh[r*192 + kc + c];
            sm->Al[r][c] = Agl[r*192 + kc + c];
        }
        #pragma unroll 2
        for (int i = tid; i < 64*16; i += 256) {
            int r = i >> 4, c = i & 15;
            sm->Bh[r][c] = Bgh[r*192 + kc + c];
            sm->Bl[r][c] = Bgl[r*192 + kc + c];
        }
        __syncthreads();
        #pragma unroll
        for (int ks = 0; ks < 2; ks++) {
            unsigned ah[2][4], al[2][4], bh[4][2], bl[4][2];
            #pragma unroll
            for (int mi = 0; mi < 2; mi++) {
                int r = mw*32 + mi*16 + g;
                ah[mi][0] = sm->Ah[r  ][ks*8 + tig];
                ah[mi][1] = sm->Ah[r+8][ks*8 + tig];
                ah[mi][2] = sm->Ah[r  ][ks*8 + tig + 4];
                ah[mi][3] = sm->Ah[r+8][ks*8 + tig + 4];
                al[mi][0] = sm->Al[r  ][ks*8 + tig];
                al[mi][1] = sm->Al[r+8][ks*8 + tig];
                al[mi][2] = sm->Al[r  ][ks*8 + tig + 4];
                al[mi][3] = sm->Al[r+8][ks*8 + tig + 4];
            }
            #pragma unroll
            for (int ni = 0; ni < 4; ni++) {
                int n = nw*32 + ni*8 + g;
                bh[ni][0] = sm->Bh[n][ks*8 + tig];
                bh[ni][1] = sm->Bh[n][ks*8 + tig + 4];
                bl[ni][0] = sm->Bl[n][ks*8 + tig];
                bl[ni][1] = sm->Bl[n][ks*8 + tig + 4];
            }
            #pragma unroll
            for (int mi = 0; mi < 2; mi++)
                #pragma unroll
                for (int ni = 0; ni < 4; ni++) {
                    mma16816(acc[mi][ni], ah[mi], bh[ni][0], bh[ni][1]);  // hi*hi
                    mma16816(acc[mi][ni], ah[mi], bl[ni][0], bl[ni][1]);  // hi*lo
                    mma16816(acc[mi][ni], al[mi], bh[ni][0], bh[ni][1]);  // lo*hi
                }
        }
    }
}

// ---------------------------------------------------------------------------
// 2) QKV projection GEMM (tensor cores); scatter split q/k/v (v transposed).
// ---------------------------------------------------------------------------
__global__ void __launch_bounds__(256) qkv_mma() {
    __shared__ GemmSmem sm;
    int m0 = blockIdx.y * 128, d0 = blockIdx.x * 64;
    int tid = threadIdx.x, w = tid >> 5, lane = tid & 31;
    int g = lane >> 2, tig = lane & 3;
    int mw = w >> 1, nw = w & 1;

    float acc[2][4][4] = {};
    gemm_mainloop(&sm,
        (const unsigned*)g_xh + (size_t)m0*192, (const unsigned*)g_xl + (size_t)m0*192,
        (const unsigned*)g_wqh + (size_t)d0*192, (const unsigned*)g_wql + (size_t)d0*192,
        tid, mw, nw, g, tig, acc);

    int which = d0 / DIMC;            // 0=q,1=k,2=v (constant: 64 | 384)
    int r0 = d0 - which*DIMC;
    #pragma unroll
    for (int mi = 0; mi < 2; mi++) {
        #pragma unroll
        for (int rr = 0; rr < 2; rr++) {
            int m = m0 + mw*32 + mi*16 + g + rr*8;
            int b = m / NTOK, n = m - b*NTOK;
            #pragma unroll
            for (int ni = 0; ni < 4; ni++) {
                #pragma unroll
                for (int jj = 0; jj < 2; jj++) {
                    int d = r0 + nw*32 + ni*8 + 2*tig + jj;
                    int h = d / DEPTH, dd = d - h*DEPTH;
                    int bhI = b*NHEAD + h;
                    float x = acc[mi][ni][rr*2 + jj];
                    __nv_bfloat16 hi = __float2bfloat16_rn(x);
                    __nv_bfloat16 lo = __float2bfloat16_rn(x - __bfloat162float(hi));
                    if (which == 0) {
                        size_t idx = ((size_t)bhI*NTOK + n)*DEPTH + dd;
                        g_qhi[idx] = hi; g_qlo[idx] = lo;
                    } else if (which == 1) {
                        size_t idx = ((size_t)bhI*NTOK + n)*DEPTH + dd;
                        g_khi[idx] = hi; g_klo[idx] = lo;
                    } else {
                        size_t idx = ((size_t)bhI*DEPTH + dd)*NTOK + n;
                        g_vthi[idx] = hi; g_vtlo[idx] = lo;
                    }
                }
            }
        }
    }
}

// ---------------------------------------------------------------------------
// 3) Tensor-core flash attention (bf16 split). Epilogue emits bf16 hi/lo.
// ---------------------------------------------------------------------------
__global__ void __launch_bounds__(128) attn_mma(const float* __restrict__ tau) {
    __shared__ __nv_bfloat16 Khs[64][56];
    __shared__ __nv_bfloat16 Kls[64][56];
    __shared__ __nv_bfloat16 Vhs[48][72];
    __shared__ __nv_bfloat16 Vls[48][72];

    int qc = blockIdx.x, h = blockIdx.y, b = blockIdx.z;
    int bh = b*NHEAD + h;
    int tid = threadIdx.x, w = tid >> 5, lane = tid & 31;
    int g = lane >> 2, tig = lane & 3;
    float scale2 = expf(tau[h]) * 1.44269504088896f;
    int m0 = qc*64 + w*16;

    const __nv_bfloat16* qh = g_qhi + (size_t)bh*NTOK*DEPTH;
    const __nv_bfloat16* ql = g_qlo + (size_t)bh*NTOK*DEPTH;
    unsigned aqh[3][4], aql[3][4];
    #pragma unroll
    for (int ks = 0; ks < 3; ks++) {
        int c0 = ks*16 + 2*tig;
        aqh[ks][0] = *(const unsigned*)(qh + (size_t)(m0+g  )*DEPTH + c0);
        aqh[ks][1] = *(const unsigned*)(qh + (size_t)(m0+g+8)*DEPTH + c0);
        aqh[ks][2] = *(const unsigned*)(qh + (size_t)(m0+g  )*DEPTH + c0 + 8);
        aqh[ks][3] = *(const unsigned*)(qh + (size_t)(m0+g+8)*DEPTH + c0 + 8);
        aql[ks][0] = *(const unsigned*)(ql + (size_t)(m0+g  )*DEPTH + c0);
        aql[ks][1] = *(const unsigned*)(ql + (size_t)(m0+g+8)*DEPTH + c0);
        aql[ks][2] = *(const unsigned*)(ql + (size_t)(m0+g  )*DEPTH + c0 + 8);
        aql[ks][3] = *(const unsigned*)(ql + (size_t)(m0+g+8)*DEPTH + c0 + 8);
    }

    float o[6][4] = {};
    float mr[2] = {-1e30f, -1e30f};
    float lp[2] = {0.f, 0.f};

    const unsigned* Kgh = (const unsigned*)(g_khi + (size_t)bh*NTOK*DEPTH);
    const unsigned* Kgl = (const unsigned*)(g_klo + (size_t)bh*NTOK*DEPTH);

    for (int j0 = 0; j0 < NTOK; j0 += 64) {
        __syncthreads();
        #pragma unroll 4
        for (int idx = tid; idx < 64*24; idx += 128) {
            int row = idx / 24, c = idx % 24;
            ((unsigned*)Khs)[row*28 + c] = Kgh[(size_t)(j0+row)*24 + c];
            ((unsigned*)Kls)[row*28 + c] = Kgl[(size_t)(j0+row)*24 + c];
        }
        #pragma unroll 4
        for (int idx = tid; idx < 48*32; idx += 128) {
            int dd = idx / 32, c = idx % 32;
            const unsigned* vh = (const unsigned*)(g_vthi + ((size_t)bh*DEPTH+dd)*NTOK + j0);
            const unsigned* vl = (const unsigned*)(g_vtlo + ((size_t)bh*DEPTH+dd)*NTOK + j0);
            ((unsigned*)Vhs)[dd*36 + c] = vh[c];
            ((unsigned*)Vls)[dd*36 + c] = vl[c];
        }
        __syncthreads();

        float s[8][4];
        #pragma unroll
        for (int nt = 0; nt < 8; nt++) { s[nt][0]=0.f; s[nt][1]=0.f; s[nt][2]=0.f; s[nt][3]=0.f; }
        #pragma unroll
        for (int nt = 0; nt < 8; nt++) {
            const __nv_bfloat16* krh = &Khs[nt*8 + g][0];
            const __nv_bfloat16* krl = &Kls[nt*8 + g][0];
            #pragma unroll
            for (int ks = 0; ks < 3; ks++) {
                unsigned bh0 = *(const unsigned*)(krh + ks*16 + 2*tig);
                unsigned bh1 = *(const unsigned*)(krh + ks*16 + 2*tig + 8);
                unsigned bl0 = *(const unsigned*)(krl + ks*16 + 2*tig);
                unsigned bl1 = *(const unsigned*)(krl + ks*16 + 2*tig + 8);
                mma16816(s[nt], aqh[ks], bh0, bh1);
                mma16816(s[nt], aqh[ks], bl0, bl1);
                mma16816(s[nt], aql[ks], bh0, bh1);
            }
        }

        float mx0 = -1e30f, mx1 = -1e30f;
        #pragma unroll
        for (int nt = 0; nt < 8; nt++) {
            s[nt][0] *= scale2; s[nt][1] *= scale2; s[nt][2] *= scale2; s[nt][3] *= scale2;
            mx0 = fmaxf(mx0, fmaxf(s[nt][0], s[nt][1]));
            mx1 = fmaxf(mx1, fmaxf(s[nt][2], s[nt][3]));
        }
        #pragma unroll
        for (int off = 1; off <= 2; off <<= 1) {
            mx0 = fmaxf(mx0, __shfl_xor_sync(0xffffffffu, mx0, off));
            mx1 = fmaxf(mx1, __shfl_xor_sync(0xffffffffu, mx1, off));
        }
        float mn0 = fmaxf(mr[0], mx0), mn1 = fmaxf(mr[1], mx1);
        float cr0 = exp2f(mr[0] - mn0), cr1 = exp2f(mr[1] - mn1);
        mr[0] = mn0; mr[1] = mn1;
        lp[0] *= cr0; lp[1] *= cr1;
        #pragma unroll
        for (int nt2 = 0; nt2 < 6; nt2++) {
            o[nt2][0] *= cr0; o[nt2][1] *= cr0;
            o[nt2][2] *= cr1; o[nt2][3] *= cr1;
        }

        unsigned Ph0[8], Ph1[8], Pl0[8], Pl1[8];
        #pragma unroll
        for (int nt = 0; nt < 8; nt++) {
            float p0 = exp2f(s[nt][0] - mr[0]);
            float p1 = exp2f(s[nt][1] - mr[0]);
            float p2 = exp2f(s[nt][2] - mr[1]);
            float p3 = exp2f(s[nt][3] - mr[1]);
            lp[0] += p0 + p1; lp[1] += p2 + p3;
            __nv_bfloat16 h0 = __float2bfloat16_rn(p0), h1 = __float2bfloat16_rn(p1);
            __nv_bfloat16 h2 = __float2bfloat16_rn(p2), h3 = __float2bfloat16_rn(p3);
            __nv_bfloat16 l0 = __float2bfloat16_rn(p0 - __bfloat162float(h0));
            __nv_bfloat16 l1 = __float2bfloat16_rn(p1 - __bfloat162float(h1));
            __nv_bfloat16 l2 = __float2bfloat16_rn(p2 - __bfloat162float(h2));
            __nv_bfloat16 l3 = __float2bfloat16_rn(p3 - __bfloat162float(h3));
            Ph0[nt] = pack2(h0, h1); Ph1[nt] = pack2(h2, h3);
            Pl0[nt] = pack2(l0, l1); Pl1[nt] = pack2(l2, l3);
        }

        #pragma unroll
        for (int nt2 = 0; nt2 < 6; nt2++) {
            const __nv_bfloat16* vrh = &Vhs[nt2*8 + g][0];
            const __nv_bfloat16* vrl = &Vls[nt2*8 + g][0];
            #pragma unroll
            for (int ksj = 0; ksj < 4; ksj++) {
                unsigned bh0 = *(const unsigned*)(vrh + ksj*16 + 2*tig);
                unsigned bh1 = *(const unsigned*)(vrh + ksj*16 + 2*tig + 8);
                unsigned bl0 = *(const unsigned*)(vrl + ksj*16 + 2*tig);
                unsigned bl1 = *(const unsigned*)(vrl + ksj*16 + 2*tig + 8);
                unsigned Ahi[4] = {Ph0[2*ksj], Ph1[2*ksj], Ph0[2*ksj+1], Ph1[2*ksj+1]};
                unsigned Alo[4] = {Pl0[2*ksj], Pl1[2*ksj], Pl0[2*ksj+1], Pl1[2*ksj+1]};
                mma16816(o[nt2], Ahi, bh0, bh1);
                mma16816(o[nt2], Ahi, bl0, bl1);
                mma16816(o[nt2], Alo, bh0, bh1);
            }
        }
    }

    #pragma unroll
    for (int off = 1; off <= 2; off <<= 1) {
        lp[0] += __shfl_xor_sync(0xffffffffu, lp[0], off);
        lp[1] += __shfl_xor_sync(0xffffffffu, lp[1], off);
    }
    float inv0 = 1.f / lp[0], inv1 = 1.f / lp[1];
    size_t base0 = ((size_t)(b*NTOK + m0 + g    ))*DIMC + h*DEPTH;
    size_t base1 = ((size_t)(b*NTOK + m0 + g + 8))*DIMC + h*DEPTH;
    #pragma unroll
    for (int nt2 = 0; nt2 < 6; nt2++) {
        float a0 = o[nt2][0]*inv0, a1 = o[nt2][1]*inv0;
        float a2 = o[nt2][2]*inv1, a3 = o[nt2][3]*inv1;
        __nv_bfloat16 h0 = __float2bfloat16_rn(a0), h1 = __float2bfloat16_rn(a1);
        __nv_bfloat16 h2 = __float2bfloat16_rn(a2), h3 = __float2bfloat16_rn(a3);
        __nv_bfloat16 l0 = __float2bfloat16_rn(a0 - __bfloat162float(h0));
        __nv_bfloat16 l1 = __float2bfloat16_rn(a1 - __bfloat162float(h1));
        __nv_bfloat16 l2 = __float2bfloat16_rn(a2 - __bfloat162float(h2));
        __nv_bfloat16 l3 = __float2bfloat16_rn(a3 - __bfloat162float(h3));
        int co = nt2*8 + 2*tig;
        *(unsigned*)(g_ah + base0 + co) = pack2(h0, h1);
        *(unsigned*)(g_al + base0 + co) = pack2(l0, l1);
        *(unsigned*)(g_ah + base1 + co) = pack2(h2, h3);
        *(unsigned*)(g_al + base1 + co) = pack2(l2, l3);
    }
}

// ---------------------------------------------------------------------------
// 4) Output projection (tensor cores) + bias + transpose to [B, C, H*W].
// ---------------------------------------------------------------------------
__global__ void __launch_bounds__(256) out_mma(const float* __restrict__ bias,
                                               float* __restrict__ out) {
    __shared__ GemmSmem sm;
    int m0 = blockIdx.y * 128, d0 = blockIdx.x * 64;
    int tid = threadIdx.x, w = tid >> 5, lane = tid & 31;
    int g = lane >> 2, tig = lane & 3;
    int mw = w >> 1, nw = w & 1;

    float acc[2][4][4] = {};
    gemm_mainloop(&sm,
        (const unsigned*)g_ah + (size_t)m0*192, (const unsigned*)g_al + (size_t)m0*192,
        (const unsigned*)g_woh + (size_t)d0*192, (const unsigned*)g_wol + (size_t)d0*192,
        tid, mw, nw, g, tig, acc);

    #pragma unroll
    for (int mi = 0; mi < 2; mi++) {
        #pragma unroll
        for (int rr = 0; rr < 2; rr++) {
            int m = m0 + mw*32 + mi*16 + g + rr*8;
            int b = m / NTOK, n = m - b*NTOK;
            #pragma unroll
            for (int ni = 0; ni < 4; ni++) {
                #pragma unroll
                for (int jj = 0; jj < 2; jj++) {
                    int d = d0 + nw*32 + ni*8 + 2*tig + jj;
                    out[((size_t)b*DIMC + d)*NTOK + n] = acc[mi][ni][rr*2 + jj] + bias[d];
                }
            }
        }
    }
}

// ---------------------------------------------------------------------------
extern "C" void kernel_launch(void* const* d_in, const int* in_sizes, int n_in,
                              void* d_out, int out_size) {
    const float* feat  = (const float*)d_in[0];
    const float* gamma = (const float*)d_in[1];
    const float* beta  = (const float*)d_in[2];
    const float* tau   = (const float*)d_in[3];
    const float* w_qkv = (const float*)d_in[4];
    const float* w_out = (const float*)d_in[5];
    const float* b_out = (const float*)d_in[6];
    float* out = (float*)d_out;

    split_w<<<(QKVD*DIMC + 255)/256, 256>>>(w_qkv, w_out);
    ln_kernel<<<BATCH*NTOK, DIMC>>>(feat, gamma, beta);
    qkv_mma<<<dim3(QKVD/64, BATCH*NTOK/128), 256>>>();
    attn_mma<<<dim3(NTOK/64, NHEAD, BATCH), 128>>>(tau);
    out_mma<<<dim3(DIMC/64, BATCH*NTOK/128), 256>>>(b_out, out);
}

// round 4
// speedup vs baseline: 3.6493x; 1.1743x over previous
#include <cuda_runtime.h>
#include <cuda_bf16.h>
#include <math.h>

#define BATCH 4
#define DIMC  384
#define NTOK  2304      // 48*48
#define NHEAD 8
#define DEPTH 48
#define QKVD  1152
#define LN_EPS 1e-5f
#define BH    (BATCH*NHEAD)
#define SM_SHIFT 40.0f

// ---------------- scratch (no allocations allowed) -------------------------
__device__ __nv_bfloat16 g_xh [BATCH*NTOK*DIMC], g_xl [BATCH*NTOK*DIMC];   // LN out split
__device__ __nv_bfloat16 g_ah [BATCH*NTOK*DIMC], g_al [BATCH*NTOK*DIMC];   // attn out split
__device__ __nv_bfloat16 g_wqh[QKVD*DIMC],       g_wql[QKVD*DIMC];
__device__ __nv_bfloat16 g_woh[DIMC*DIMC],       g_wol[DIMC*DIMC];
__device__ __nv_bfloat16 g_qhi[BH*NTOK*DEPTH], g_qlo[BH*NTOK*DEPTH];   // [bh,n,d]
__device__ __nv_bfloat16 g_khi[BH*NTOK*DEPTH], g_klo[BH*NTOK*DEPTH];   // [bh,n,d]
__device__ __nv_bfloat16 g_vthi[BH*DEPTH*NTOK], g_vtlo[BH*DEPTH*NTOK]; // [bh,d,n]

__inline__ __device__ float warpsum(float v) {
    #pragma unroll
    for (int o = 16; o > 0; o >>= 1) v += __shfl_down_sync(0xffffffffu, v, o);
    return v;
}

__device__ __forceinline__ void mma16816(float* d, const unsigned* a, unsigned b0, unsigned b1) {
    asm volatile(
        "mma.sync.aligned.m16n8k16.row.col.f32.bf16.bf16.f32 "
        "{%0,%1,%2,%3},{%4,%5,%6,%7},{%8,%9},{%0,%1,%2,%3};"
        : "+f"(d[0]), "+f"(d[1]), "+f"(d[2]), "+f"(d[3])
        : "r"(a[0]), "r"(a[1]), "r"(a[2]), "r"(a[3]), "r"(b0), "r"(b1));
}

__device__ __forceinline__ unsigned pack2(__nv_bfloat16 a, __nv_bfloat16 b) {
    __nv_bfloat162 t = __halves2bfloat162(a, b);
    return *(unsigned*)&t;
}

__device__ __forceinline__ void cpasync16(unsigned dst, const void* src) {
    asm volatile("cp.async.cg.shared.global [%0], [%1], 16;" :: "r"(dst), "l"(src));
}
__device__ __forceinline__ unsigned smem_u32(const void* p) {
    unsigned a;
    asm("{ .reg .u64 t; cvta.to.shared.u64 t, %1; cvt.u32.u64 %0, t; }" : "=r"(a) : "l"(p));
    return a;
}

// attn smem stage layout (bytes)
#define ST_KH 0
#define ST_KL 7168
#define ST_VH 14336
#define ST_VL 21248
#define ST_SZ 28160

// ---------------------------------------------------------------------------
// 0) split weights into bf16 hi/lo
// ---------------------------------------------------------------------------
__global__ void split_w(const float* __restrict__ wq, const float* __restrict__ wo) {
    int i = blockIdx.x*256 + threadIdx.x;
    if (i < QKVD*DIMC) {
        float x = wq[i];
        __nv_bfloat16 hi = __float2bfloat16_rn(x);
        g_wqh[i] = hi; g_wql[i] = __float2bfloat16_rn(x - __bfloat162float(hi));
    }
    if (i < DIMC*DIMC) {
        float x = wo[i];
        __nv_bfloat16 hi = __float2bfloat16_rn(x);
        g_woh[i] = hi; g_wol[i] = __float2bfloat16_rn(x - __bfloat162float(hi));
    }
}

// ---------------------------------------------------------------------------
// 1) LayerNorm + NCHW->NLC transpose; emits bf16 hi/lo split.
// ---------------------------------------------------------------------------
__global__ void ln_kernel(const float* __restrict__ feat,
                          const float* __restrict__ gamma,
                          const float* __restrict__ beta) {
    int bn = blockIdx.x;
    int b  = bn / NTOK, n = bn % NTOK;
    int c  = threadIdx.x;
    float v = feat[(b*DIMC + c)*NTOK + n];

    float s  = warpsum(v);
    float s2 = warpsum(v*v);
    __shared__ float ws[12], ws2[12];
    __shared__ float mean_s, rstd_s;
    int warp = c >> 5, lane = c & 31;
    if (lane == 0) { ws[warp] = s; ws2[warp] = s2; }
    __syncthreads();
    if (c < 32) {
        float t  = (c < 12) ? ws[c]  : 0.f;
        float t2 = (c < 12) ? ws2[c] : 0.f;
        t = warpsum(t); t2 = warpsum(t2);
        if (c == 0) {
            float mu  = t * (1.f/DIMC);
            float var = t2 * (1.f/DIMC) - mu*mu;
            mean_s = mu;
            rstd_s = rsqrtf(var + LN_EPS);
        }
    }
    __syncthreads();
    float x = (v - mean_s) * rstd_s * gamma[c] + beta[c];
    __nv_bfloat16 hi = __float2bfloat16_rn(x);
    g_xh[bn*DIMC + c] = hi;
    g_xl[bn*DIMC + c] = __float2bfloat16_rn(x - __bfloat162float(hi));
}

// ---------------------------------------------------------------------------
// Tensor-core GEMM mainloop: C[128x64] += A[128x384] * B[64x384]^T
// ---------------------------------------------------------------------------
struct GemmSmem {
    unsigned Ah[128][20], Al[128][20], Bh[64][20], Bl[64][20];
};

__device__ __forceinline__ void gemm_mainloop(
        GemmSmem* sm,
        const unsigned* Agh, const unsigned* Agl,
        const unsigned* Bgh, const unsigned* Bgl,
        int tid, int mw, int nw, int g, int tig,
        float acc[2][4][4]) {
    for (int kc = 0; kc < 192; kc += 16) {
        __syncthreads();
        #pragma unroll 4
        for (int i = tid; i < 128*16; i += 256) {
            int r = i >> 4, c = i & 15;
            sm->Ah[r][c] = Agh[r*192 + kc + c];
            sm->Al[r][c] = Agl[r*192 + kc + c];
        }
        #pragma unroll 2
        for (int i = tid; i < 64*16; i += 256) {
            int r = i >> 4, c = i & 15;
            sm->Bh[r][c] = Bgh[r*192 + kc + c];
            sm->Bl[r][c] = Bgl[r*192 + kc + c];
        }
        __syncthreads();
        #pragma unroll
        for (int ks = 0; ks < 2; ks++) {
            unsigned ah[2][4], al[2][4], bh[4][2], bl[4][2];
            #pragma unroll
            for (int mi = 0; mi < 2; mi++) {
                int r = mw*32 + mi*16 + g;
                ah[mi][0] = sm->Ah[r  ][ks*8 + tig];
                ah[mi][1] = sm->Ah[r+8][ks*8 + tig];
                ah[mi][2] = sm->Ah[r  ][ks*8 + tig + 4];
                ah[mi][3] = sm->Ah[r+8][ks*8 + tig + 4];
                al[mi][0] = sm->Al[r  ][ks*8 + tig];
                al[mi][1] = sm->Al[r+8][ks*8 + tig];
                al[mi][2] = sm->Al[r  ][ks*8 + tig + 4];
                al[mi][3] = sm->Al[r+8][ks*8 + tig + 4];
            }
            #pragma unroll
            for (int ni = 0; ni < 4; ni++) {
                int n = nw*32 + ni*8 + g;
                bh[ni][0] = sm->Bh[n][ks*8 + tig];
                bh[ni][1] = sm->Bh[n][ks*8 + tig + 4];
                bl[ni][0] = sm->Bl[n][ks*8 + tig];
                bl[ni][1] = sm->Bl[n][ks*8 + tig + 4];
            }
            #pragma unroll
            for (int mi = 0; mi < 2; mi++)
                #pragma unroll
                for (int ni = 0; ni < 4; ni++) {
                    mma16816(acc[mi][ni], ah[mi], bh[ni][0], bh[ni][1]);
                    mma16816(acc[mi][ni], ah[mi], bl[ni][0], bl[ni][1]);
                    mma16816(acc[mi][ni], al[mi], bh[ni][0], bh[ni][1]);
                }
        }
    }
}

// ---------------------------------------------------------------------------
// 2) QKV projection GEMM (tensor cores); scatter split q/k/v (v transposed).
// ---------------------------------------------------------------------------
__global__ void __launch_bounds__(256) qkv_mma() {
    __shared__ GemmSmem sm;
    int m0 = blockIdx.y * 128, d0 = blockIdx.x * 64;
    int tid = threadIdx.x, w = tid >> 5, lane = tid & 31;
    int g = lane >> 2, tig = lane & 3;
    int mw = w >> 1, nw = w & 1;

    float acc[2][4][4] = {};
    gemm_mainloop(&sm,
        (const unsigned*)g_xh + (size_t)m0*192, (const unsigned*)g_xl + (size_t)m0*192,
        (const unsigned*)g_wqh + (size_t)d0*192, (const unsigned*)g_wql + (size_t)d0*192,
        tid, mw, nw, g, tig, acc);

    int which = d0 / DIMC;
    int r0 = d0 - which*DIMC;
    #pragma unroll
    for (int mi = 0; mi < 2; mi++) {
        #pragma unroll
        for (int rr = 0; rr < 2; rr++) {
            int m = m0 + mw*32 + mi*16 + g + rr*8;
            int b = m / NTOK, n = m - b*NTOK;
            #pragma unroll
            for (int ni = 0; ni < 4; ni++) {
                #pragma unroll
                for (int jj = 0; jj < 2; jj++) {
                    int d = r0 + nw*32 + ni*8 + 2*tig + jj;
                    int h = d / DEPTH, dd = d - h*DEPTH;
                    int bhI = b*NHEAD + h;
                    float x = acc[mi][ni][rr*2 + jj];
                    __nv_bfloat16 hi = __float2bfloat16_rn(x);
                    __nv_bfloat16 lo = __float2bfloat16_rn(x - __bfloat162float(hi));
                    if (which == 0) {
                        size_t idx = ((size_t)bhI*NTOK + n)*DEPTH + dd;
                        g_qhi[idx] = hi; g_qlo[idx] = lo;
                    } else if (which == 1) {
                        size_t idx = ((size_t)bhI*NTOK + n)*DEPTH + dd;
                        g_khi[idx] = hi; g_klo[idx] = lo;
                    } else {
                        size_t idx = ((size_t)bhI*DEPTH + dd)*NTOK + n;
                        g_vthi[idx] = hi; g_vtlo[idx] = lo;
                    }
                }
            }
        }
    }
}

// ---------------------------------------------------------------------------
// 3) Tensor-core flash attention, fixed-shift softmax (no running max),
//    cp.async double-buffered K/V tiles.
// ---------------------------------------------------------------------------
__global__ void __launch_bounds__(128) attn_mma(const float* __restrict__ tau) {
    extern __shared__ char dsm[];

    int qc = blockIdx.x, h = blockIdx.y, b = blockIdx.z;
    int bh = b*NHEAD + h;
    int tid = threadIdx.x, w = tid >> 5, lane = tid & 31;
    int g = lane >> 2, tig = lane & 3;
    float scale2 = expf(tau[h]) * 1.44269504088896f;
    int m0 = qc*64 + w*16;

    const char* Kh_src = (const char*)(g_khi + (size_t)bh*NTOK*DEPTH);
    const char* Kl_src = (const char*)(g_klo + (size_t)bh*NTOK*DEPTH);
    const char* Vh_src = (const char*)(g_vthi + (size_t)bh*DEPTH*NTOK);
    const char* Vl_src = (const char*)(g_vtlo + (size_t)bh*DEPTH*NTOK);
    unsigned sbase = smem_u32(dsm);

    // ---- Q fragments (persistent)
    const __nv_bfloat16* qh = g_qhi + (size_t)bh*NTOK*DEPTH;
    const __nv_bfloat16* ql = g_qlo + (size_t)bh*NTOK*DEPTH;
    unsigned aqh[3][4], aql[3][4];
    #pragma unroll
    for (int ks = 0; ks < 3; ks++) {
        int c0 = ks*16 + 2*tig;
        aqh[ks][0] = *(const unsigned*)(qh + (size_t)(m0+g  )*DEPTH + c0);
        aqh[ks][1] = *(const unsigned*)(qh + (size_t)(m0+g+8)*DEPTH + c0);
        aqh[ks][2] = *(const unsigned*)(qh + (size_t)(m0+g  )*DEPTH + c0 + 8);
        aqh[ks][3] = *(const unsigned*)(qh + (size_t)(m0+g+8)*DEPTH + c0 + 8);
        aql[ks][0] = *(const unsigned*)(ql + (size_t)(m0+g  )*DEPTH + c0);
        aql[ks][1] = *(const unsigned*)(ql + (size_t)(m0+g+8)*DEPTH + c0);
        aql[ks][2] = *(const unsigned*)(ql + (size_t)(m0+g  )*DEPTH + c0 + 8);
        aql[ks][3] = *(const unsigned*)(ql + (size_t)(m0+g+8)*DEPTH + c0 + 8);
    }

    float o[6][4] = {};
    float lp[2] = {0.f, 0.f};

    // ---- async tile loader: K rows 96B (6x16), V rows 128B (8x16)
    auto load_tile = [&](int j0, int st) {
        unsigned base = sbase + st*ST_SZ;
        #pragma unroll 3
        for (int i = tid; i < 384; i += 128) {
            int row = i / 6, c = i % 6;
            size_t src = (size_t)(j0 + row)*96 + c*16;
            cpasync16(base + ST_KH + row*112 + c*16, Kh_src + src);
            cpasync16(base + ST_KL + row*112 + c*16, Kl_src + src);
        }
        #pragma unroll 3
        for (int i = tid; i < 384; i += 128) {
            int row = i / 8, c = i % 8;
            size_t src = ((size_t)row*NTOK + j0)*2 + c*16;
            cpasync16(base + ST_VH + row*144 + c*16, Vh_src + src);
            cpasync16(base + ST_VL + row*144 + c*16, Vl_src + src);
        }
        asm volatile("cp.async.commit_group;");
    };

    load_tile(0, 0);

    for (int t = 0; t < NTOK/64; t++) {
        int st = t & 1;
        asm volatile("cp.async.wait_group 0;" ::: "memory");
        __syncthreads();
        if (t + 1 < NTOK/64) load_tile((t+1)*64, st ^ 1);

        const __nv_bfloat16* Kh = (const __nv_bfloat16*)(dsm + st*ST_SZ + ST_KH);
        const __nv_bfloat16* Kl = (const __nv_bfloat16*)(dsm + st*ST_SZ + ST_KL);
        const __nv_bfloat16* Vh = (const __nv_bfloat16*)(dsm + st*ST_SZ + ST_VH);
        const __nv_bfloat16* Vl = (const __nv_bfloat16*)(dsm + st*ST_SZ + ST_VL);

        // ---- S = Q K^T (3-term split)
        float s[8][4];
        #pragma unroll
        for (int nt = 0; nt < 8; nt++) { s[nt][0]=0.f; s[nt][1]=0.f; s[nt][2]=0.f; s[nt][3]=0.f; }
        #pragma unroll
        for (int nt = 0; nt < 8; nt++) {
            const __nv_bfloat16* krh = Kh + (nt*8 + g)*56;
            const __nv_bfloat16* krl = Kl + (nt*8 + g)*56;
            #pragma unroll
            for (int ks = 0; ks < 3; ks++) {
                unsigned bh0 = *(const unsigned*)(krh + ks*16 + 2*tig);
                unsigned bh1 = *(const unsigned*)(krh + ks*16 + 2*tig + 8);
                unsigned bl0 = *(const unsigned*)(krl + ks*16 + 2*tig);
                unsigned bl1 = *(const unsigned*)(krl + ks*16 + 2*tig + 8);
                mma16816(s[nt], aqh[ks], bh0, bh1);
                mma16816(s[nt], aqh[ks], bl0, bl1);
                mma16816(s[nt], aql[ks], bh0, bh1);
            }
        }

        // ---- P = exp2(s*scale2 - SHIFT): no running max needed (bounded scores)
        unsigned Ph0[8], Ph1[8], Pl0[8], Pl1[8];
        #pragma unroll
        for (int nt = 0; nt < 8; nt++) {
            float p0 = exp2f(fmaf(s[nt][0], scale2, -SM_SHIFT));
            float p1 = exp2f(fmaf(s[nt][1], scale2, -SM_SHIFT));
            float p2 = exp2f(fmaf(s[nt][2], scale2, -SM_SHIFT));
            float p3 = exp2f(fmaf(s[nt][3], scale2, -SM_SHIFT));
            lp[0] += p0 + p1; lp[1] += p2 + p3;
            __nv_bfloat16 h0 = __float2bfloat16_rn(p0), h1 = __float2bfloat16_rn(p1);
            __nv_bfloat16 h2 = __float2bfloat16_rn(p2), h3 = __float2bfloat16_rn(p3);
            __nv_bfloat16 l0 = __float2bfloat16_rn(p0 - __bfloat162float(h0));
            __nv_bfloat16 l1 = __float2bfloat16_rn(p1 - __bfloat162float(h1));
            __nv_bfloat16 l2 = __float2bfloat16_rn(p2 - __bfloat162float(h2));
            __nv_bfloat16 l3 = __float2bfloat16_rn(p3 - __bfloat162float(h3));
            Ph0[nt] = pack2(h0, h1); Ph1[nt] = pack2(h2, h3);
            Pl0[nt] = pack2(l0, l1); Pl1[nt] = pack2(l2, l3);
        }

        // ---- O += P V (3-term split)
        #pragma unroll
        for (int nt2 = 0; nt2 < 6; nt2++) {
            const __nv_bfloat16* vrh = Vh + (nt2*8 + g)*72;
            const __nv_bfloat16* vrl = Vl + (nt2*8 + g)*72;
            #pragma unroll
            for (int ksj = 0; ksj < 4; ksj++) {
                unsigned bh0 = *(const unsigned*)(vrh + ksj*16 + 2*tig);
                unsigned bh1 = *(const unsigned*)(vrh + ksj*16 + 2*tig + 8);
                unsigned bl0 = *(const unsigned*)(vrl + ksj*16 + 2*tig);
                unsigned bl1 = *(const unsigned*)(vrl + ksj*16 + 2*tig + 8);
                unsigned Ahi[4] = {Ph0[2*ksj], Ph1[2*ksj], Ph0[2*ksj+1], Ph1[2*ksj+1]};
                unsigned Alo[4] = {Pl0[2*ksj], Pl1[2*ksj], Pl0[2*ksj+1], Pl1[2*ksj+1]};
                mma16816(o[nt2], Ahi, bh0, bh1);
                mma16816(o[nt2], Ahi, bl0, bl1);
                mma16816(o[nt2], Alo, bh0, bh1);
            }
        }
        __syncthreads();
    }

    // ---- finalize
    #pragma unroll
    for (int off = 1; off <= 2; off <<= 1) {
        lp[0] += __shfl_xor_sync(0xffffffffu, lp[0], off);
        lp[1] += __shfl_xor_sync(0xffffffffu, lp[1], off);
    }
    float inv0 = 1.f / lp[0], inv1 = 1.f / lp[1];
    size_t base0 = ((size_t)(b*NTOK + m0 + g    ))*DIMC + h*DEPTH;
    size_t base1 = ((size_t)(b*NTOK + m0 + g + 8))*DIMC + h*DEPTH;
    #pragma unroll
    for (int nt2 = 0; nt2 < 6; nt2++) {
        float a0 = o[nt2][0]*inv0, a1 = o[nt2][1]*inv0;
        float a2 = o[nt2][2]*inv1, a3 = o[nt2][3]*inv1;
        __nv_bfloat16 h0 = __float2bfloat16_rn(a0), h1 = __float2bfloat16_rn(a1);
        __nv_bfloat16 h2 = __float2bfloat16_rn(a2), h3 = __float2bfloat16_rn(a3);
        __nv_bfloat16 l0 = __float2bfloat16_rn(a0 - __bfloat162float(h0));
        __nv_bfloat16 l1 = __float2bfloat16_rn(a1 - __bfloat162float(h1));
        __nv_bfloat16 l2 = __float2bfloat16_rn(a2 - __bfloat162float(h2));
        __nv_bfloat16 l3 = __float2bfloat16_rn(a3 - __bfloat162float(h3));
        int co = nt2*8 + 2*tig;
        *(unsigned*)(g_ah + base0 + co) = pack2(h0, h1);
        *(unsigned*)(g_al + base0 + co) = pack2(l0, l1);
        *(unsigned*)(g_ah + base1 + co) = pack2(h2, h3);
        *(unsigned*)(g_al + base1 + co) = pack2(l2, l3);
    }
}

// ---------------------------------------------------------------------------
// 4) Output projection (tensor cores) + bias + transpose to [B, C, H*W].
// ---------------------------------------------------------------------------
__global__ void __launch_bounds__(256) out_mma(const float* __restrict__ bias,
                                               float* __restrict__ out) {
    __shared__ GemmSmem sm;
    int m0 = blockIdx.y * 128, d0 = blockIdx.x * 64;
    int tid = threadIdx.x, w = tid >> 5, lane = tid & 31;
    int g = lane >> 2, tig = lane & 3;
    int mw = w >> 1, nw = w & 1;

    float acc[2][4][4] = {};
    gemm_mainloop(&sm,
        (const unsigned*)g_ah + (size_t)m0*192, (const unsigned*)g_al + (size_t)m0*192,
        (const unsigned*)g_woh + (size_t)d0*192, (const unsigned*)g_wol + (size_t)d0*192,
        tid, mw, nw, g, tig, acc);

    #pragma unroll
    for (int mi = 0; mi < 2; mi++) {
        #pragma unroll
        for (int rr = 0; rr < 2; rr++) {
            int m = m0 + mw*32 + mi*16 + g + rr*8;
            int b = m / NTOK, n = m - b*NTOK;
            #pragma unroll
            for (int ni = 0; ni < 4; ni++) {
                #pragma unroll
                for (int jj = 0; jj < 2; jj++) {
                    int d = d0 + nw*32 + ni*8 + 2*tig + jj;
                    out[((size_t)b*DIMC + d)*NTOK + n] = acc[mi][ni][rr*2 + jj] + bias[d];
                }
            }
        }
    }
}

// ---------------------------------------------------------------------------
extern "C" void kernel_launch(void* const* d_in, const int* in_sizes, int n_in,
                              void* d_out, int out_size) {
    const float* feat  = (const float*)d_in[0];
    const float* gamma = (const float*)d_in[1];
    const float* beta  = (const float*)d_in[2];
    const float* tau   = (const float*)d_in[3];
    const float* w_qkv = (const float*)d_in[4];
    const float* w_out = (const float*)d_in[5];
    const float* b_out = (const float*)d_in[6];
    float* out = (float*)d_out;

    static int smem_set = 0;
    if (!smem_set) {
        cudaFuncSetAttribute(attn_mma, cudaFuncAttributeMaxDynamicSharedMemorySize, 2*ST_SZ);
        smem_set = 1;
    }

    split_w<<<(QKVD*DIMC + 255)/256, 256>>>(w_qkv, w_out);
    ln_kernel<<<BATCH*NTOK, DIMC>>>(feat, gamma, beta);
    qkv_mma<<<dim3(QKVD/64, BATCH*NTOK/128), 256>>>();
    attn_mma<<<dim3(NTOK/64, NHEAD, BATCH), 128, 2*ST_SZ>>>(tau);
    out_mma<<<dim3(DIMC/64, BATCH*NTOK/128), 256>>>(b_out, out);
}

// round 5
// speedup vs baseline: 3.9217x; 1.0746x over previous
#include <cuda_runtime.h>
#include <cuda_bf16.h>
#include <math.h>

#define BATCH 4
#define DIMC  384
#define NTOK  2304      // 48*48
#define NHEAD 8
#define DEPTH 48
#define QKVD  1152
#define LN_EPS 1e-5f
#define BH    (BATCH*NHEAD)
#define SM_SHIFT 40.0f

// ---------------- scratch (no allocations allowed) -------------------------
__device__ __nv_bfloat16 g_xh [BATCH*NTOK*DIMC], g_xl [BATCH*NTOK*DIMC];   // LN out split
__device__ __nv_bfloat16 g_ah [BATCH*NTOK*DIMC], g_al [BATCH*NTOK*DIMC];   // attn out split
__device__ __nv_bfloat16 g_wqh[QKVD*DIMC],       g_wql[QKVD*DIMC];
__device__ __nv_bfloat16 g_woh[DIMC*DIMC],       g_wol[DIMC*DIMC];
__device__ __nv_bfloat16 g_qhi[BH*NTOK*DEPTH], g_qlo[BH*NTOK*DEPTH];   // [bh,n,d]
__device__ __nv_bfloat16 g_khi[BH*NTOK*DEPTH], g_klo[BH*NTOK*DEPTH];   // [bh,n,d]
__device__ __nv_bfloat16 g_vthi[BH*DEPTH*NTOK], g_vtlo[BH*DEPTH*NTOK]; // [bh,d,n]

__device__ __forceinline__ void mma16816(float* d, const unsigned* a, unsigned b0, unsigned b1) {
    asm volatile(
        "mma.sync.aligned.m16n8k16.row.col.f32.bf16.bf16.f32 "
        "{%0,%1,%2,%3},{%4,%5,%6,%7},{%8,%9},{%0,%1,%2,%3};"
        : "+f"(d[0]), "+f"(d[1]), "+f"(d[2]), "+f"(d[3])
        : "r"(a[0]), "r"(a[1]), "r"(a[2]), "r"(a[3]), "r"(b0), "r"(b1));
}

__device__ __forceinline__ unsigned pack2(__nv_bfloat16 a, __nv_bfloat16 b) {
    __nv_bfloat162 t = __halves2bfloat162(a, b);
    return *(unsigned*)&t;
}

__device__ __forceinline__ void cpasync16(unsigned dst, const void* src) {
    asm volatile("cp.async.cg.shared.global [%0], [%1], 16;" :: "r"(dst), "l"(src));
}
__device__ __forceinline__ unsigned smem_u32(const void* p) {
    unsigned a;
    asm("{ .reg .u64 t; cvta.to.shared.u64 t, %1; cvt.u32.u64 %0, t; }" : "=r"(a) : "l"(p));
    return a;
}

// attn smem stage layout (bytes)
#define ST_KH 0
#define ST_KL 7168
#define ST_VH 14336
#define ST_VL 21248
#define ST_SZ 28160

// gemm smem stage layout (32-bit words)
#define GA_H 0
#define GA_L 2560
#define GB_H 5120
#define GB_L 6400
#define G_STW 7680                 // words per stage
#define G_STB (G_STW*4)            // 30720 bytes
#define G_SMEM (2*G_STB)           // 61440

// ---------------------------------------------------------------------------
// 0) split weights into bf16 hi/lo
// ---------------------------------------------------------------------------
__global__ void split_w(const float* __restrict__ wq, const float* __restrict__ wo) {
    int i = blockIdx.x*256 + threadIdx.x;
    if (i < QKVD*DIMC) {
        float x = wq[i];
        __nv_bfloat16 hi = __float2bfloat16_rn(x);
        g_wqh[i] = hi; g_wql[i] = __float2bfloat16_rn(x - __bfloat162float(hi));
    }
    if (i < DIMC*DIMC) {
        float x = wo[i];
        __nv_bfloat16 hi = __float2bfloat16_rn(x);
        g_woh[i] = hi; g_wol[i] = __float2bfloat16_rn(x - __bfloat162float(hi));
    }
}

// ---------------------------------------------------------------------------
// 1) LayerNorm, coalesced: block = 64 tokens x 384 ch. Thread owns a token
//    (along n => coalesced loads), register accumulation, smem-transposed
//    coalesced bf16 writes.
// ---------------------------------------------------------------------------
__global__ void __launch_bounds__(256) ln_kernel(const float* __restrict__ feat,
                          const float* __restrict__ gamma,
                          const float* __restrict__ beta) {
    __shared__ float ps[4][64], ps2[4][64];
    __shared__ float s_mean[64], s_rstd[64];
    __shared__ __nv_bfloat16 tbh[64][66], tbl[64][66];   // [n][c] chunk

    int n0 = blockIdx.x * 64, b = blockIdx.y;
    int t = threadIdx.x;
    int nj = t & 63, ci4 = t >> 6;          // thread -> token nj, c-subset ci4
    const float* fb = feat + (size_t)b*DIMC*NTOK + n0;

    // pass 1: accumulate sum / sumsq (coalesced along n)
    float s = 0.f, s2 = 0.f;
    for (int c = ci4; c < DIMC; c += 4) {
        float v = fb[(size_t)c*NTOK + nj];
        s += v; s2 += v*v;
    }
    ps[ci4][nj] = s; ps2[ci4][nj] = s2;
    __syncthreads();
    if (t < 64) {
        float ts  = ps[0][t] + ps[1][t] + ps[2][t] + ps[3][t];
        float ts2 = ps2[0][t] + ps2[1][t] + ps2[2][t] + ps2[3][t];
        float mu  = ts * (1.f/DIMC);
        float var = ts2 * (1.f/DIMC) - mu*mu;
        s_mean[t] = mu;
        s_rstd[t] = rsqrtf(var + LN_EPS);
    }
    __syncthreads();

    float mu = s_mean[nj], rs = s_rstd[nj];

    // pass 2: apply (L2-hot re-read), transpose chunks of 64 c, coalesced writes
    for (int c0 = 0; c0 < DIMC; c0 += 64) {
        #pragma unroll
        for (int cc = 0; cc < 16; cc++) {
            int cl = cc*4 + ci4;
            int c = c0 + cl;
            float v = fb[(size_t)c*NTOK + nj];
            float x = (v - mu) * rs * gamma[c] + beta[c];
            __nv_bfloat16 hi = __float2bfloat16_rn(x);
            tbh[nj][cl] = hi;
            tbl[nj][cl] = __float2bfloat16_rn(x - __bfloat162float(hi));
        }
        __syncthreads();
        #pragma unroll
        for (int i = t; i < 64*64; i += 256) {
            int nl = i >> 6, cl = i & 63;
            size_t dst = ((size_t)(b*NTOK + n0 + nl))*DIMC + c0 + cl;
            g_xh[dst] = tbh[nl][cl];
            g_xl[dst] = tbl[nl][cl];
        }
        __syncthreads();
    }
}

// ---------------------------------------------------------------------------
// Tensor-core GEMM mainloop: C[128x64] += A[128x384]*B[64x384]^T, cp.async
// double-buffered k-chunks (12 chunks of 16 words).
// ---------------------------------------------------------------------------
__device__ __forceinline__ void gemm_mainloop(
        char* dsm,
        const unsigned* Agh, const unsigned* Agl,
        const unsigned* Bgh, const unsigned* Bgl,
        int tid, int mw, int nw, int g, int tig,
        float acc[2][4][4]) {
    unsigned sbase = smem_u32(dsm);
    unsigned* smw = (unsigned*)dsm;

    auto loadc = [&](int kcw, int st) {
        unsigned base = sbase + st*G_STB;
        #pragma unroll 2
        for (int i = tid; i < 512; i += 256) {
            int r = i >> 2, c4 = (i & 3) * 4;
            cpasync16(base + (GA_H + r*20 + c4)*4, Agh + r*192 + kcw + c4);
            cpasync16(base + (GA_L + r*20 + c4)*4, Agl + r*192 + kcw + c4);
        }
        for (int i = tid; i < 256; i += 256) {
            int r = i >> 2, c4 = (i & 3) * 4;
            cpasync16(base + (GB_H + r*20 + c4)*4, Bgh + r*192 + kcw + c4);
            cpasync16(base + (GB_L + r*20 + c4)*4, Bgl + r*192 + kcw + c4);
        }
        asm volatile("cp.async.commit_group;");
    };

    loadc(0, 0);
    for (int t = 0; t < 12; t++) {
        int st = t & 1;
        asm volatile("cp.async.wait_group 0;" ::: "memory");
        __syncthreads();
        if (t + 1 < 12) loadc((t+1)*16, st ^ 1);

        const unsigned* Ah = smw + st*G_STW + GA_H;
        const unsigned* Al = smw + st*G_STW + GA_L;
        const unsigned* Bh = smw + st*G_STW + GB_H;
        const unsigned* Bl = smw + st*G_STW + GB_L;

        #pragma unroll
        for (int ks = 0; ks < 2; ks++) {
            unsigned ah[2][4], al[2][4], bh[4][2], bl[4][2];
            #pragma unroll
            for (int mi = 0; mi < 2; mi++) {
                int r = mw*32 + mi*16 + g;
                ah[mi][0] = Ah[r*20     + ks*8 + tig];
                ah[mi][1] = Ah[(r+8)*20 + ks*8 + tig];
                ah[mi][2] = Ah[r*20     + ks*8 + tig + 4];
                ah[mi][3] = Ah[(r+8)*20 + ks*8 + tig + 4];
                al[mi][0] = Al[r*20     + ks*8 + tig];
                al[mi][1] = Al[(r+8)*20 + ks*8 + tig];
                al[mi][2] = Al[r*20     + ks*8 + tig + 4];
                al[mi][3] = Al[(r+8)*20 + ks*8 + tig + 4];
            }
            #pragma unroll
            for (int ni = 0; ni < 4; ni++) {
                int n = nw*32 + ni*8 + g;
                bh[ni][0] = Bh[n*20 + ks*8 + tig];
                bh[ni][1] = Bh[n*20 + ks*8 + tig + 4];
                bl[ni][0] = Bl[n*20 + ks*8 + tig];
                bl[ni][1] = Bl[n*20 + ks*8 + tig + 4];
            }
            #pragma unroll
            for (int mi = 0; mi < 2; mi++)
                #pragma unroll
                for (int ni = 0; ni < 4; ni++) {
                    mma16816(acc[mi][ni], ah[mi], bh[ni][0], bh[ni][1]);
                    mma16816(acc[mi][ni], ah[mi], bl[ni][0], bl[ni][1]);
                    mma16816(acc[mi][ni], al[mi], bh[ni][0], bh[ni][1]);
                }
        }
    }
}

// ---------------------------------------------------------------------------
// 2) QKV projection GEMM; q/k direct scatter, V transposed through smem.
// ---------------------------------------------------------------------------
__global__ void __launch_bounds__(256) qkv_mma() {
    extern __shared__ char dsm[];
    int m0 = blockIdx.y * 128, d0 = blockIdx.x * 64;
    int tid = threadIdx.x, w = tid >> 5, lane = tid & 31;
    int g = lane >> 2, tig = lane & 3;
    int mw = w >> 1, nw = w & 1;

    float acc[2][4][4] = {};
    gemm_mainloop(dsm,
        (const unsigned*)g_xh + (size_t)m0*192, (const unsigned*)g_xl + (size_t)m0*192,
        (const unsigned*)g_wqh + (size_t)d0*192, (const unsigned*)g_wql + (size_t)d0*192,
        tid, mw, nw, g, tig, acc);

    int which = d0 / DIMC;
    int r0 = d0 - which*DIMC;
    int bb = m0 / NTOK, n0 = m0 - bb*NTOK;   // 128-token tile never crosses batch

    if (which < 2) {
        #pragma unroll
        for (int mi = 0; mi < 2; mi++) {
            #pragma unroll
            for (int rr = 0; rr < 2; rr++) {
                int n = n0 + mw*32 + mi*16 + g + rr*8;
                #pragma unroll
                for (int ni = 0; ni < 4; ni++) {
                    #pragma unroll
                    for (int jj = 0; jj < 2; jj++) {
                        int d = r0 + nw*32 + ni*8 + 2*tig + jj;
                        int h = d / DEPTH, dd = d - h*DEPTH;
                        int bhI = bb*NHEAD + h;
                        float x = acc[mi][ni][rr*2 + jj];
                        __nv_bfloat16 hi = __float2bfloat16_rn(x);
                        __nv_bfloat16 lo = __float2bfloat16_rn(x - __bfloat162float(hi));
                        size_t idx = ((size_t)bhI*NTOK + n)*DEPTH + dd;
                        if (which == 0) { g_qhi[idx] = hi; g_qlo[idx] = lo; }
                        else            { g_khi[idx] = hi; g_klo[idx] = lo; }
                    }
                }
            }
        }
    } else {
        // V: transpose through smem -> coalesced [bh, d, n] writes
        __syncthreads();
        __nv_bfloat16* th = (__nv_bfloat16*)dsm;           // [64][130]
        __nv_bfloat16* tl = th + 64*130;
        #pragma unroll
        for (int mi = 0; mi < 2; mi++)
            #pragma unroll
            for (int rr = 0; rr < 2; rr++) {
                int ml = mw*32 + mi*16 + g + rr*8;
                #pragma unroll
                for (int ni = 0; ni < 4; ni++)
                    #pragma unroll
                    for (int jj = 0; jj < 2; jj++) {
                        int dl = nw*32 + ni*8 + 2*tig + jj;
                        float x = acc[mi][ni][rr*2 + jj];
                        __nv_bfloat16 hi = __float2bfloat16_rn(x);
                        th[dl*130 + ml] = hi;
                        tl[dl*130 + ml] = __float2bfloat16_rn(x - __bfloat162float(hi));
                    }
            }
        __syncthreads();
        #pragma unroll
        for (int i = tid; i < 64*128; i += 256) {
            int dl = i >> 7, n = i & 127;
            int rg = r0 + dl;
            int h = rg / DEPTH, dd = rg - h*DEPTH;
            size_t idx = ((size_t)(bb*NHEAD + h)*DEPTH + dd)*NTOK + n0 + n;
            g_vthi[idx] = th[dl*130 + n];
            g_vtlo[idx] = tl[dl*130 + n];
        }
    }
}

// ---------------------------------------------------------------------------
// 3) Tensor-core flash attention, fixed-shift softmax, cp.async double-buffer.
// ---------------------------------------------------------------------------
__global__ void __launch_bounds__(128) attn_mma(const float* __restrict__ tau) {
    extern __shared__ char dsm[];

    int qc = blockIdx.x, h = blockIdx.y, b = blockIdx.z;
    int bh = b*NHEAD + h;
    int tid = threadIdx.x, w = tid >> 5, lane = tid & 31;
    int g = lane >> 2, tig = lane & 3;
    float scale2 = expf(tau[h]) * 1.44269504088896f;
    int m0 = qc*64 + w*16;

    const char* Kh_src = (const char*)(g_khi + (size_t)bh*NTOK*DEPTH);
    const char* Kl_src = (const char*)(g_klo + (size_t)bh*NTOK*DEPTH);
    const char* Vh_src = (const char*)(g_vthi + (size_t)bh*DEPTH*NTOK);
    const char* Vl_src = (const char*)(g_vtlo + (size_t)bh*DEPTH*NTOK);
    unsigned sbase = smem_u32(dsm);

    const __nv_bfloat16* qh = g_qhi + (size_t)bh*NTOK*DEPTH;
    const __nv_bfloat16* ql = g_qlo + (size_t)bh*NTOK*DEPTH;
    unsigned aqh[3][4], aql[3][4];
    #pragma unroll
    for (int ks = 0; ks < 3; ks++) {
        int c0 = ks*16 + 2*tig;
        aqh[ks][0] = *(const unsigned*)(qh + (size_t)(m0+g  )*DEPTH + c0);
        aqh[ks][1] = *(const unsigned*)(qh + (size_t)(m0+g+8)*DEPTH + c0);
        aqh[ks][2] = *(const unsigned*)(qh + (size_t)(m0+g  )*DEPTH + c0 + 8);
        aqh[ks][3] = *(const unsigned*)(qh + (size_t)(m0+g+8)*DEPTH + c0 + 8);
        aql[ks][0] = *(const unsigned*)(ql + (size_t)(m0+g  )*DEPTH + c0);
        aql[ks][1] = *(const unsigned*)(ql + (size_t)(m0+g+8)*DEPTH + c0);
        aql[ks][2] = *(const unsigned*)(ql + (size_t)(m0+g  )*DEPTH + c0 + 8);
        aql[ks][3] = *(const unsigned*)(ql + (size_t)(m0+g+8)*DEPTH + c0 + 8);
    }

    float o[6][4] = {};
    float lp[2] = {0.f, 0.f};

    auto load_tile = [&](int j0, int st) {
        unsigned base = sbase + st*ST_SZ;
        #pragma unroll 3
        for (int i = tid; i < 384; i += 128) {
            int row = i / 6, c = i % 6;
            size_t src = (size_t)(j0 + row)*96 + c*16;
            cpasync16(base + ST_KH + row*112 + c*16, Kh_src + src);
            cpasync16(base + ST_KL + row*112 + c*16, Kl_src + src);
        }
        #pragma unroll 3
        for (int i = tid; i < 384; i += 128) {
            int row = i / 8, c = i % 8;
            size_t src = ((size_t)row*NTOK + j0)*2 + c*16;
            cpasync16(base + ST_VH + row*144 + c*16, Vh_src + src);
            cpasync16(base + ST_VL + row*144 + c*16, Vl_src + src);
        }
        asm volatile("cp.async.commit_group;");
    };

    load_tile(0, 0);

    for (int t = 0; t < NTOK/64; t++) {
        int st = t & 1;
        asm volatile("cp.async.wait_group 0;" ::: "memory");
        __syncthreads();
        if (t + 1 < NTOK/64) load_tile((t+1)*64, st ^ 1);

        const __nv_bfloat16* Kh = (const __nv_bfloat16*)(dsm + st*ST_SZ + ST_KH);
        const __nv_bfloat16* Kl = (const __nv_bfloat16*)(dsm + st*ST_SZ + ST_KL);
        const __nv_bfloat16* Vh = (const __nv_bfloat16*)(dsm + st*ST_SZ + ST_VH);
        const __nv_bfloat16* Vl = (const __nv_bfloat16*)(dsm + st*ST_SZ + ST_VL);

        float s[8][4];
        #pragma unroll
        for (int nt = 0; nt < 8; nt++) { s[nt][0]=0.f; s[nt][1]=0.f; s[nt][2]=0.f; s[nt][3]=0.f; }
        #pragma unroll
        for (int nt = 0; nt < 8; nt++) {
            const __nv_bfloat16* krh = Kh + (nt*8 + g)*56;
            const __nv_bfloat16* krl = Kl + (nt*8 + g)*56;
            #pragma unroll
            for (int ks = 0; ks < 3; ks++) {
                unsigned bh0 = *(const unsigned*)(krh + ks*16 + 2*tig);
                unsigned bh1 = *(const unsigned*)(krh + ks*16 + 2*tig + 8);
                unsigned bl0 = *(const unsigned*)(krl + ks*16 + 2*tig);
                unsigned bl1 = *(const unsigned*)(krl + ks*16 + 2*tig + 8);
                mma16816(s[nt], aqh[ks], bh0, bh1);
                mma16816(s[nt], aqh[ks], bl0, bl1);
                mma16816(s[nt], aql[ks], bh0, bh1);
            }
        }

        unsigned Ph0[8], Ph1[8], Pl0[8], Pl1[8];
        #pragma unroll
        for (int nt = 0; nt < 8; nt++) {
            float p0 = exp2f(fmaf(s[nt][0], scale2, -SM_SHIFT));
            float p1 = exp2f(fmaf(s[nt][1], scale2, -SM_SHIFT));
            float p2 = exp2f(fmaf(s[nt][2], scale2, -SM_SHIFT));
            float p3 = exp2f(fmaf(s[nt][3], scale2, -SM_SHIFT));
            lp[0] += p0 + p1; lp[1] += p2 + p3;
            __nv_bfloat16 h0 = __float2bfloat16_rn(p0), h1 = __float2bfloat16_rn(p1);
            __nv_bfloat16 h2 = __float2bfloat16_rn(p2), h3 = __float2bfloat16_rn(p3);
            __nv_bfloat16 l0 = __float2bfloat16_rn(p0 - __bfloat162float(h0));
            __nv_bfloat16 l1 = __float2bfloat16_rn(p1 - __bfloat162float(h1));
            __nv_bfloat16 l2 = __float2bfloat16_rn(p2 - __bfloat162float(h2));
            __nv_bfloat16 l3 = __float2bfloat16_rn(p3 - __bfloat162float(h3));
            Ph0[nt] = pack2(h0, h1); Ph1[nt] = pack2(h2, h3);
            Pl0[nt] = pack2(l0, l1); Pl1[nt] = pack2(l2, l3);
        }

        #pragma unroll
        for (int nt2 = 0; nt2 < 6; nt2++) {
            const __nv_bfloat16* vrh = Vh + (nt2*8 + g)*72;
            const __nv_bfloat16* vrl = Vl + (nt2*8 + g)*72;
            #pragma unroll
            for (int ksj = 0; ksj < 4; ksj++) {
                unsigned bh0 = *(const unsigned*)(vrh + ksj*16 + 2*tig);
                unsigned bh1 = *(const unsigned*)(vrh + ksj*16 + 2*tig + 8);
                unsigned bl0 = *(const unsigned*)(vrl + ksj*16 + 2*tig);
                unsigned bl1 = *(const unsigned*)(vrl + ksj*16 + 2*tig + 8);
                unsigned Ahi[4] = {Ph0[2*ksj], Ph1[2*ksj], Ph0[2*ksj+1], Ph1[2*ksj+1]};
                unsigned Alo[4] = {Pl0[2*ksj], Pl1[2*ksj], Pl0[2*ksj+1], Pl1[2*ksj+1]};
                mma16816(o[nt2], Ahi, bh0, bh1);
                mma16816(o[nt2], Ahi, bl0, bl1);
                mma16816(o[nt2], Alo, bh0, bh1);
            }
        }
        __syncthreads();
    }

    #pragma unroll
    for (int off = 1; off <= 2; off <<= 1) {
        lp[0] += __shfl_xor_sync(0xffffffffu, lp[0], off);
        lp[1] += __shfl_xor_sync(0xffffffffu, lp[1], off);
    }
    float inv0 = 1.f / lp[0], inv1 = 1.f / lp[1];
    size_t base0 = ((size_t)(b*NTOK + m0 + g    ))*DIMC + h*DEPTH;
    size_t base1 = ((size_t)(b*NTOK + m0 + g + 8))*DIMC + h*DEPTH;
    #pragma unroll
    for (int nt2 = 0; nt2 < 6; nt2++) {
        float a0 = o[nt2][0]*inv0, a1 = o[nt2][1]*inv0;
        float a2 = o[nt2][2]*inv1, a3 = o[nt2][3]*inv1;
        __nv_bfloat16 h0 = __float2bfloat16_rn(a0), h1 = __float2bfloat16_rn(a1);
        __nv_bfloat16 h2 = __float2bfloat16_rn(a2), h3 = __float2bfloat16_rn(a3);
        __nv_bfloat16 l0 = __float2bfloat16_rn(a0 - __bfloat162float(h0));
        __nv_bfloat16 l1 = __float2bfloat16_rn(a1 - __bfloat162float(h1));
        __nv_bfloat16 l2 = __float2bfloat16_rn(a2 - __bfloat162float(h2));
        __nv_bfloat16 l3 = __float2bfloat16_rn(a3 - __bfloat162float(h3));
        int co = nt2*8 + 2*tig;
        *(unsigned*)(g_ah + base0 + co) = pack2(h0, h1);
        *(unsigned*)(g_al + base0 + co) = pack2(l0, l1);
        *(unsigned*)(g_ah + base1 + co) = pack2(h2, h3);
        *(unsigned*)(g_al + base1 + co) = pack2(l2, l3);
    }
}

// ---------------------------------------------------------------------------
// 4) Output projection + bias; smem-transposed coalesced [B,C,N] writes.
// ---------------------------------------------------------------------------
__global__ void __launch_bounds__(256) out_mma(const float* __restrict__ bias,
                                               float* __restrict__ out) {
    extern __shared__ char dsm[];
    int m0 = blockIdx.y * 128, d0 = blockIdx.x * 64;
    int tid = threadIdx.x, w = tid >> 5, lane = tid & 31;
    int g = lane >> 2, tig = lane & 3;
    int mw = w >> 1, nw = w & 1;

    float acc[2][4][4] = {};
    gemm_mainloop(dsm,
        (const unsigned*)g_ah + (size_t)m0*192, (const unsigned*)g_al + (size_t)m0*192,
        (const unsigned*)g_woh + (size_t)d0*192, (const unsigned*)g_wol + (size_t)d0*192,
        tid, mw, nw, g, tig, acc);

    int bb = m0 / NTOK, n0 = m0 - bb*NTOK;
    __syncthreads();
    float* fb = (float*)dsm;                 // [128][65]
    #pragma unroll
    for (int mi = 0; mi < 2; mi++)
        #pragma unroll
        for (int rr = 0; rr < 2; rr++) {
            int ml = mw*32 + mi*16 + g + rr*8;
            #pragma unroll
            for (int ni = 0; ni < 4; ni++)
                #pragma unroll
                for (int jj = 0; jj < 2; jj++) {
                    int dl = nw*32 + ni*8 + 2*tig + jj;
                    fb[ml*65 + dl] = acc[mi][ni][rr*2 + jj] + bias[d0 + dl];
                }
        }
    __syncthreads();
    #pragma unroll
    for (int i = tid; i < 64*128; i += 256) {
        int dl = i >> 7, n = i & 127;
        out[((size_t)bb*DIMC + d0 + dl)*NTOK + n0 + n] = fb[n*65 + dl];
    }
}

// ---------------------------------------------------------------------------
extern "C" void kernel_launch(void* const* d_in, const int* in_sizes, int n_in,
                              void* d_out, int out_size) {
    const float* feat  = (const float*)d_in[0];
    const float* gamma = (const float*)d_in[1];
    const float* beta  = (const float*)d_in[2];
    const float* tau   = (const float*)d_in[3];
    const float* w_qkv = (const float*)d_in[4];
    const float* w_out = (const float*)d_in[5];
    const float* b_out = (const float*)d_in[6];
    float* out = (float*)d_out;

    static int smem_set = 0;
    if (!smem_set) {
        cudaFuncSetAttribute(attn_mma, cudaFuncAttributeMaxDynamicSharedMemorySize, 2*ST_SZ);
        cudaFuncSetAttribute(qkv_mma, cudaFuncAttributeMaxDynamicSharedMemorySize, G_SMEM);
        cudaFuncSetAttribute(out_mma, cudaFuncAttributeMaxDynamicSharedMemorySize, G_SMEM);
        smem_set = 1;
    }

    split_w<<<(QKVD*DIMC + 255)/256, 256>>>(w_qkv, w_out);
    ln_kernel<<<dim3(NTOK/64, BATCH), 256>>>(feat, gamma, beta);
    qkv_mma<<<dim3(QKVD/64, BATCH*NTOK/128), 256, G_SMEM>>>();
    attn_mma<<<dim3(NTOK/64, NHEAD, BATCH), 128, 2*ST_SZ>>>(tau);
    out_mma<<<dim3(DIMC/64, BATCH*NTOK/128), 256, G_SMEM>>>(b_out, out);
}

// round 6
// speedup vs baseline: 4.2830x; 1.0921x over previous
#include <cuda_runtime.h>
#include <cuda_bf16.h>
#include <math.h>

#define BATCH 4
#define DIMC  384
#define NTOK  2304      // 48*48
#define NHEAD 8
#define DEPTH 48
#define QKVD  1152
#define LN_EPS 1e-5f
#define BH    (BATCH*NHEAD)
#define SM_SHIFT 40.0f

// ---------------- scratch (no allocations allowed) -------------------------
__device__ __nv_bfloat16 g_xh [BATCH*NTOK*DIMC], g_xl [BATCH*NTOK*DIMC];
__device__ __nv_bfloat16 g_ah [BATCH*NTOK*DIMC], g_al [BATCH*NTOK*DIMC];
__device__ __nv_bfloat16 g_wqh[QKVD*DIMC],       g_wql[QKVD*DIMC];
__device__ __nv_bfloat16 g_woh[DIMC*DIMC],       g_wol[DIMC*DIMC];
__device__ __nv_bfloat16 g_qhi[BH*NTOK*DEPTH], g_qlo[BH*NTOK*DEPTH];
__device__ __nv_bfloat16 g_khi[BH*NTOK*DEPTH], g_klo[BH*NTOK*DEPTH];
__device__ __nv_bfloat16 g_vthi[BH*DEPTH*NTOK], g_vtlo[BH*DEPTH*NTOK];

__device__ __forceinline__ void mma16816(float* d, const unsigned* a, unsigned b0, unsigned b1) {
    asm volatile(
        "mma.sync.aligned.m16n8k16.row.col.f32.bf16.bf16.f32 "
        "{%0,%1,%2,%3},{%4,%5,%6,%7},{%8,%9},{%0,%1,%2,%3};"
        : "+f"(d[0]), "+f"(d[1]), "+f"(d[2]), "+f"(d[3])
        : "r"(a[0]), "r"(a[1]), "r"(a[2]), "r"(a[3]), "r"(b0), "r"(b1));
}

__device__ __forceinline__ unsigned pack2(__nv_bfloat16 a, __nv_bfloat16 b) {
    __nv_bfloat162 t = __halves2bfloat162(a, b);
    return *(unsigned*)&t;
}

// packed split: (p0,p1) -> hi bf16x2 (p0 lower), lo bf16x2 residuals
__device__ __forceinline__ void split2(float p0, float p1, unsigned& hi, unsigned& lo) {
    unsigned hbits;
    asm("cvt.rn.bf16x2.f32 %0, %1, %2;" : "=r"(hbits) : "f"(p1), "f"(p0));
    float h0 = __uint_as_float(hbits << 16);
    float h1 = __uint_as_float(hbits & 0xFFFF0000u);
    unsigned lbits;
    asm("cvt.rn.bf16x2.f32 %0, %1, %2;" : "=r"(lbits) : "f"(p1 - h1), "f"(p0 - h0));
    hi = hbits; lo = lbits;
}

__device__ __forceinline__ void cpasync16(unsigned dst, const void* src) {
    asm volatile("cp.async.cg.shared.global [%0], [%1], 16;" :: "r"(dst), "l"(src));
}
__device__ __forceinline__ unsigned smem_u32(const void* p) {
    unsigned a;
    asm("{ .reg .u64 t; cvta.to.shared.u64 t, %1; cvt.u32.u64 %0, t; }" : "=r"(a) : "l"(p));
    return a;
}

// attn smem stage layout (bytes)
#define ST_KH 0
#define ST_KL 7168
#define ST_VH 14336
#define ST_VL 21248
#define ST_SZ 28160

// gemm smem stage layout (32-bit words)
#define GA_H 0
#define GA_L 2560
#define GB_H 5120
#define GB_L 6400
#define G_STW 7680
#define G_STB (G_STW*4)
#define G_SMEM (2*G_STB)

// ---------------------------------------------------------------------------
__global__ void split_w(const float* __restrict__ wq, const float* __restrict__ wo) {
    int i = blockIdx.x*256 + threadIdx.x;
    if (i < QKVD*DIMC) {
        float x = wq[i];
        __nv_bfloat16 hi = __float2bfloat16_rn(x);
        g_wqh[i] = hi; g_wql[i] = __float2bfloat16_rn(x - __bfloat162float(hi));
    }
    if (i < DIMC*DIMC) {
        float x = wo[i];
        __nv_bfloat16 hi = __float2bfloat16_rn(x);
        g_woh[i] = hi; g_wol[i] = __float2bfloat16_rn(x - __bfloat162float(hi));
    }
}

// ---------------------------------------------------------------------------
// 1) LayerNorm, coalesced; register accumulation; smem-transposed writes.
// ---------------------------------------------------------------------------
__global__ void __launch_bounds__(256) ln_kernel(const float* __restrict__ feat,
                          const float* __restrict__ gamma,
                          const float* __restrict__ beta) {
    __shared__ float ps[4][64], ps2[4][64];
    __shared__ float s_mean[64], s_rstd[64];
    __shared__ __nv_bfloat16 tbh[64][66], tbl[64][66];

    int n0 = blockIdx.x * 64, b = blockIdx.y;
    int t = threadIdx.x;
    int nj = t & 63, ci4 = t >> 6;
    const float* fb = feat + (size_t)b*DIMC*NTOK + n0;

    float s = 0.f, s2 = 0.f;
    for (int c = ci4; c < DIMC; c += 4) {
        float v = fb[(size_t)c*NTOK + nj];
        s += v; s2 += v*v;
    }
    ps[ci4][nj] = s; ps2[ci4][nj] = s2;
    __syncthreads();
    if (t < 64) {
        float ts  = ps[0][t] + ps[1][t] + ps[2][t] + ps[3][t];
        float ts2 = ps2[0][t] + ps2[1][t] + ps2[2][t] + ps2[3][t];
        float mu  = ts * (1.f/DIMC);
        float var = ts2 * (1.f/DIMC) - mu*mu;
        s_mean[t] = mu;
        s_rstd[t] = rsqrtf(var + LN_EPS);
    }
    __syncthreads();

    float mu = s_mean[nj], rs = s_rstd[nj];

    for (int c0 = 0; c0 < DIMC; c0 += 64) {
        #pragma unroll
        for (int cc = 0; cc < 16; cc++) {
            int cl = cc*4 + ci4;
            int c = c0 + cl;
            float v = fb[(size_t)c*NTOK + nj];
            float x = (v - mu) * rs * gamma[c] + beta[c];
            __nv_bfloat16 hi = __float2bfloat16_rn(x);
            tbh[nj][cl] = hi;
            tbl[nj][cl] = __float2bfloat16_rn(x - __bfloat162float(hi));
        }
        __syncthreads();
        #pragma unroll
        for (int i = t; i < 64*64; i += 256) {
            int nl = i >> 6, cl = i & 63;
            size_t dst = ((size_t)(b*NTOK + n0 + nl))*DIMC + c0 + cl;
            g_xh[dst] = tbh[nl][cl];
            g_xl[dst] = tbl[nl][cl];
        }
        __syncthreads();
    }
}

// ---------------------------------------------------------------------------
// Tensor-core GEMM mainloop, cp.async double-buffered; term-major MMA order
// (8 independent accumulators between same-acc reuse).
// ---------------------------------------------------------------------------
__device__ __forceinline__ void gemm_mainloop(
        char* dsm,
        const unsigned* Agh, const unsigned* Agl,
        const unsigned* Bgh, const unsigned* Bgl,
        int tid, int mw, int nw, int g, int tig,
        float acc[2][4][4]) {
    unsigned sbase = smem_u32(dsm);
    unsigned* smw = (unsigned*)dsm;

    auto loadc = [&](int kcw, int st) {
        unsigned base = sbase + st*G_STB;
        #pragma unroll 2
        for (int i = tid; i < 512; i += 256) {
            int r = i >> 2, c4 = (i & 3) * 4;
            cpasync16(base + (GA_H + r*20 + c4)*4, Agh + r*192 + kcw + c4);
            cpasync16(base + (GA_L + r*20 + c4)*4, Agl + r*192 + kcw + c4);
        }
        for (int i = tid; i < 256; i += 256) {
            int r = i >> 2, c4 = (i & 3) * 4;
            cpasync16(base + (GB_H + r*20 + c4)*4, Bgh + r*192 + kcw + c4);
            cpasync16(base + (GB_L + r*20 + c4)*4, Bgl + r*192 + kcw + c4);
        }
        asm volatile("cp.async.commit_group;");
    };

    loadc(0, 0);
    for (int t = 0; t < 12; t++) {
        int st = t & 1;
        asm volatile("cp.async.wait_group 0;" ::: "memory");
        __syncthreads();
        if (t + 1 < 12) loadc((t+1)*16, st ^ 1);

        const unsigned* Ah = smw + st*G_STW + GA_H;
        const unsigned* Al = smw + st*G_STW + GA_L;
        const unsigned* Bh = smw + st*G_STW + GB_H;
        const unsigned* Bl = smw + st*G_STW + GB_L;

        #pragma unroll
        for (int ks = 0; ks < 2; ks++) {
            unsigned ah[2][4], al[2][4], bh[4][2], bl[4][2];
            #pragma unroll
            for (int mi = 0; mi < 2; mi++) {
                int r = mw*32 + mi*16 + g;
                ah[mi][0] = Ah[r*20     + ks*8 + tig];
                ah[mi][1] = Ah[(r+8)*20 + ks*8 + tig];
                ah[mi][2] = Ah[r*20     + ks*8 + tig + 4];
                ah[mi][3] = Ah[(r+8)*20 + ks*8 + tig + 4];
                al[mi][0] = Al[r*20     + ks*8 + tig];
                al[mi][1] = Al[(r+8)*20 + ks*8 + tig];
                al[mi][2] = Al[r*20     + ks*8 + tig + 4];
                al[mi][3] = Al[(r+8)*20 + ks*8 + tig + 4];
            }
            #pragma unroll
            for (int ni = 0; ni < 4; ni++) {
                int n = nw*32 + ni*8 + g;
                bh[ni][0] = Bh[n*20 + ks*8 + tig];
                bh[ni][1] = Bh[n*20 + ks*8 + tig + 4];
                bl[ni][0] = Bl[n*20 + ks*8 + tig];
                bl[ni][1] = Bl[n*20 + ks*8 + tig + 4];
            }
            // term-major: rotate through all 8 accumulators per term
            #pragma unroll
            for (int mi = 0; mi < 2; mi++)
                #pragma unroll
                for (int ni = 0; ni < 4; ni++)
                    mma16816(acc[mi][ni], ah[mi], bh[ni][0], bh[ni][1]);
            #pragma unroll
            for (int mi = 0; mi < 2; mi++)
                #pragma unroll
                for (int ni = 0; ni < 4; ni++)
                    mma16816(acc[mi][ni], ah[mi], bl[ni][0], bl[ni][1]);
            #pragma unroll
            for (int mi = 0; mi < 2; mi++)
                #pragma unroll
                for (int ni = 0; ni < 4; ni++)
                    mma16816(acc[mi][ni], al[mi], bh[ni][0], bh[ni][1]);
        }
    }
}

// ---------------------------------------------------------------------------
// 2) QKV projection GEMM; q/k direct scatter, V transposed through smem.
// ---------------------------------------------------------------------------
__global__ void __launch_bounds__(256) qkv_mma() {
    extern __shared__ char dsm[];
    int m0 = blockIdx.y * 128, d0 = blockIdx.x * 64;
    int tid = threadIdx.x, w = tid >> 5, lane = tid & 31;
    int g = lane >> 2, tig = lane & 3;
    int mw = w >> 1, nw = w & 1;

    float acc[2][4][4] = {};
    gemm_mainloop(dsm,
        (const unsigned*)g_xh + (size_t)m0*192, (const unsigned*)g_xl + (size_t)m0*192,
        (const unsigned*)g_wqh + (size_t)d0*192, (const unsigned*)g_wql + (size_t)d0*192,
        tid, mw, nw, g, tig, acc);

    int which = d0 / DIMC;
    int r0 = d0 - which*DIMC;
    int bb = m0 / NTOK, n0 = m0 - bb*NTOK;

    if (which < 2) {
        #pragma unroll
        for (int mi = 0; mi < 2; mi++) {
            #pragma unroll
            for (int rr = 0; rr < 2; rr++) {
                int n = n0 + mw*32 + mi*16 + g + rr*8;
                #pragma unroll
                for (int ni = 0; ni < 4; ni++) {
                    int d = r0 + nw*32 + ni*8 + 2*tig;
                    int h = d / DEPTH, dd = d - h*DEPTH;
                    int bhI = bb*NHEAD + h;
                    unsigned hi, lo;
                    split2(acc[mi][ni][rr*2], acc[mi][ni][rr*2+1], hi, lo);
                    size_t idx = ((size_t)bhI*NTOK + n)*DEPTH + dd;
                    if (which == 0) { *(unsigned*)(g_qhi+idx) = hi; *(unsigned*)(g_qlo+idx) = lo; }
                    else            { *(unsigned*)(g_khi+idx) = hi; *(unsigned*)(g_klo+idx) = lo; }
                }
            }
        }
    } else {
        __syncthreads();
        __nv_bfloat16* th = (__nv_bfloat16*)dsm;           // [64][130]
        __nv_bfloat16* tl = th + 64*130;
        #pragma unroll
        for (int mi = 0; mi < 2; mi++)
            #pragma unroll
            for (int rr = 0; rr < 2; rr++) {
                int ml = mw*32 + mi*16 + g + rr*8;
                #pragma unroll
                for (int ni = 0; ni < 4; ni++)
                    #pragma unroll
                    for (int jj = 0; jj < 2; jj++) {
                        int dl = nw*32 + ni*8 + 2*tig + jj;
                        float x = acc[mi][ni][rr*2 + jj];
                        __nv_bfloat16 hi = __float2bfloat16_rn(x);
                        th[dl*130 + ml] = hi;
                        tl[dl*130 + ml] = __float2bfloat16_rn(x - __bfloat162float(hi));
                    }
            }
        __syncthreads();
        #pragma unroll
        for (int i = tid; i < 64*128; i += 256) {
            int dl = i >> 7, n = i & 127;
            int rg = r0 + dl;
            int h = rg / DEPTH, dd = rg - h*DEPTH;
            size_t idx = ((size_t)(bb*NHEAD + h)*DEPTH + dd)*NTOK + n0 + n;
            g_vthi[idx] = th[dl*130 + n];
            g_vtlo[idx] = tl[dl*130 + n];
        }
    }
}

// ---------------------------------------------------------------------------
// 3) Tensor-core flash attention; fixed-shift softmax; term-major MMA order.
// ---------------------------------------------------------------------------
__global__ void __launch_bounds__(128) attn_mma(const float* __restrict__ tau) {
    extern __shared__ char dsm[];

    int qc = blockIdx.x, h = blockIdx.y, b = blockIdx.z;
    int bh = b*NHEAD + h;
    int tid = threadIdx.x, w = tid >> 5, lane = tid & 31;
    int g = lane >> 2, tig = lane & 3;
    float scale2 = expf(tau[h]) * 1.44269504088896f;
    int m0 = qc*64 + w*16;

    const char* Kh_src = (const char*)(g_khi + (size_t)bh*NTOK*DEPTH);
    const char* Kl_src = (const char*)(g_klo + (size_t)bh*NTOK*DEPTH);
    const char* Vh_src = (const char*)(g_vthi + (size_t)bh*DEPTH*NTOK);
    const char* Vl_src = (const char*)(g_vtlo + (size_t)bh*DEPTH*NTOK);
    unsigned sbase = smem_u32(dsm);

    const __nv_bfloat16* qh = g_qhi + (size_t)bh*NTOK*DEPTH;
    const __nv_bfloat16* ql = g_qlo + (size_t)bh*NTOK*DEPTH;
    unsigned aqh[3][4], aql[3][4];
    #pragma unroll
    for (int ks = 0; ks < 3; ks++) {
        int c0 = ks*16 + 2*tig;
        aqh[ks][0] = *(const unsigned*)(qh + (size_t)(m0+g  )*DEPTH + c0);
        aqh[ks][1] = *(const unsigned*)(qh + (size_t)(m0+g+8)*DEPTH + c0);
        aqh[ks][2] = *(const unsigned*)(qh + (size_t)(m0+g  )*DEPTH + c0 + 8);
        aqh[ks][3] = *(const unsigned*)(qh + (size_t)(m0+g+8)*DEPTH + c0 + 8);
        aql[ks][0] = *(const unsigned*)(ql + (size_t)(m0+g  )*DEPTH + c0);
        aql[ks][1] = *(const unsigned*)(ql + (size_t)(m0+g+8)*DEPTH + c0);
        aql[ks][2] = *(const unsigned*)(ql + (size_t)(m0+g  )*DEPTH + c0 + 8);
        aql[ks][3] = *(const unsigned*)(ql + (size_t)(m0+g+8)*DEPTH + c0 + 8);
    }

    float o[6][4] = {};
    float lp[2] = {0.f, 0.f};

    auto load_tile = [&](int j0, int st) {
        unsigned base = sbase + st*ST_SZ;
        #pragma unroll 3
        for (int i = tid; i < 384; i += 128) {
            int row = i / 6, c = i % 6;
            size_t src = (size_t)(j0 + row)*96 + c*16;
            cpasync16(base + ST_KH + row*112 + c*16, Kh_src + src);
            cpasync16(base + ST_KL + row*112 + c*16, Kl_src + src);
        }
        #pragma unroll 3
        for (int i = tid; i < 384; i += 128) {
            int row = i / 8, c = i % 8;
            size_t src = ((size_t)row*NTOK + j0)*2 + c*16;
            cpasync16(base + ST_VH + row*144 + c*16, Vh_src + src);
            cpasync16(base + ST_VL + row*144 + c*16, Vl_src + src);
        }
        asm volatile("cp.async.commit_group;");
    };

    load_tile(0, 0);

    for (int t = 0; t < NTOK/64; t++) {
        int st = t & 1;
        asm volatile("cp.async.wait_group 0;" ::: "memory");
        __syncthreads();
        if (t + 1 < NTOK/64) load_tile((t+1)*64, st ^ 1);

        const __nv_bfloat16* Kh = (const __nv_bfloat16*)(dsm + st*ST_SZ + ST_KH);
        const __nv_bfloat16* Kl = (const __nv_bfloat16*)(dsm + st*ST_SZ + ST_KL);
        const __nv_bfloat16* Vh = (const __nv_bfloat16*)(dsm + st*ST_SZ + ST_VH);
        const __nv_bfloat16* Vl = (const __nv_bfloat16*)(dsm + st*ST_SZ + ST_VL);

        // ---- S = Q K^T: groups of 4 accumulators, term-major inside group
        float s[8][4];
        #pragma unroll
        for (int nt = 0; nt < 8; nt++) { s[nt][0]=0.f; s[nt][1]=0.f; s[nt][2]=0.f; s[nt][3]=0.f; }
        #pragma unroll
        for (int ks = 0; ks < 3; ks++) {
            #pragma unroll
            for (int h4 = 0; h4 < 8; h4 += 4) {
                unsigned kb0[4], kb1[4], kl0[4], kl1[4];
                #pragma unroll
                for (int j = 0; j < 4; j++) {
                    const __nv_bfloat16* krh = Kh + (h4*8 + j*8 + g)*56 + ks*16 + 2*tig;
                    const __nv_bfloat16* krl = Kl + (h4*8 + j*8 + g)*56 + ks*16 + 2*tig;
                    kb0[j] = *(const unsigned*)(krh);
                    kb1[j] = *(const unsigned*)(krh + 8);
                    kl0[j] = *(const unsigned*)(krl);
                    kl1[j] = *(const unsigned*)(krl + 8);
                }
                #pragma unroll
                for (int j = 0; j < 4; j++) mma16816(s[h4+j], aqh[ks], kb0[j], kb1[j]);
                #pragma unroll
                for (int j = 0; j < 4; j++) mma16816(s[h4+j], aqh[ks], kl0[j], kl1[j]);
                #pragma unroll
                for (int j = 0; j < 4; j++) mma16816(s[h4+j], aql[ks], kb0[j], kb1[j]);
            }
        }

        // ---- P = exp2(s*scale2 - SHIFT), packed splits
        unsigned Ph0[8], Ph1[8], Pl0[8], Pl1[8];
        #pragma unroll
        for (int nt = 0; nt < 8; nt++) {
            float p0 = exp2f(fmaf(s[nt][0], scale2, -SM_SHIFT));
            float p1 = exp2f(fmaf(s[nt][1], scale2, -SM_SHIFT));
            float p2 = exp2f(fmaf(s[nt][2], scale2, -SM_SHIFT));
            float p3 = exp2f(fmaf(s[nt][3], scale2, -SM_SHIFT));
            lp[0] += p0 + p1; lp[1] += p2 + p3;
            split2(p0, p1, Ph0[nt], Pl0[nt]);
            split2(p2, p3, Ph1[nt], Pl1[nt]);
        }

        // ---- O += P V: ksj-outer, rotate over 6 accumulators per term
        #pragma unroll
        for (int ksj = 0; ksj < 4; ksj++) {
            unsigned vh0[6], vh1[6], vl0[6], vl1[6];
            #pragma unroll
            for (int nt2 = 0; nt2 < 6; nt2++) {
                const __nv_bfloat16* vrh = Vh + (nt2*8 + g)*72 + ksj*16 + 2*tig;
                const __nv_bfloat16* vrl = Vl + (nt2*8 + g)*72 + ksj*16 + 2*tig;
                vh0[nt2] = *(const unsigned*)(vrh);
                vh1[nt2] = *(const unsigned*)(vrh + 8);
                vl0[nt2] = *(const unsigned*)(vrl);
                vl1[nt2] = *(const unsigned*)(vrl + 8);
            }
            unsigned Ahi[4] = {Ph0[2*ksj], Ph1[2*ksj], Ph0[2*ksj+1], Ph1[2*ksj+1]};
            unsigned Alo[4] = {Pl0[2*ksj], Pl1[2*ksj], Pl0[2*ksj+1], Pl1[2*ksj+1]};
            #pragma unroll
            for (int nt2 = 0; nt2 < 6; nt2++) mma16816(o[nt2], Ahi, vh0[nt2], vh1[nt2]);
            #pragma unroll
            for (int nt2 = 0; nt2 < 6; nt2++) mma16816(o[nt2], Ahi, vl0[nt2], vl1[nt2]);
            #pragma unroll
            for (int nt2 = 0; nt2 < 6; nt2++) mma16816(o[nt2], Alo, vh0[nt2], vh1[nt2]);
        }
        __syncthreads();
    }

    #pragma unroll
    for (int off = 1; off <= 2; off <<= 1) {
        lp[0] += __shfl_xor_sync(0xffffffffu, lp[0], off);
        lp[1] += __shfl_xor_sync(0xffffffffu, lp[1], off);
    }
    float inv0 = 1.f / lp[0], inv1 = 1.f / lp[1];
    size_t base0 = ((size_t)(b*NTOK + m0 + g    ))*DIMC + h*DEPTH;
    size_t base1 = ((size_t)(b*NTOK + m0 + g + 8))*DIMC + h*DEPTH;
    #pragma unroll
    for (int nt2 = 0; nt2 < 6; nt2++) {
        unsigned hi0, lo0, hi1, lo1;
        split2(o[nt2][0]*inv0, o[nt2][1]*inv0, hi0, lo0);
        split2(o[nt2][2]*inv1, o[nt2][3]*inv1, hi1, lo1);
        int co = nt2*8 + 2*tig;
        *(unsigned*)(g_ah + base0 + co) = hi0;
        *(unsigned*)(g_al + base0 + co) = lo0;
        *(unsigned*)(g_ah + base1 + co) = hi1;
        *(unsigned*)(g_al + base1 + co) = lo1;
    }
}

// ---------------------------------------------------------------------------
// 4) Output projection + bias; smem-transposed coalesced [B,C,N] writes.
// ---------------------------------------------------------------------------
__global__ void __launch_bounds__(256) out_mma(const float* __restrict__ bias,
                                               float* __restrict__ out) {
    extern __shared__ char dsm[];
    int m0 = blockIdx.y * 128, d0 = blockIdx.x * 64;
    int tid = threadIdx.x, w = tid >> 5, lane = tid & 31;
    int g = lane >> 2, tig = lane & 3;
    int mw = w >> 1, nw = w & 1;

    float acc[2][4][4] = {};
    gemm_mainloop(dsm,
        (const unsigned*)g_ah + (size_t)m0*192, (const unsigned*)g_al + (size_t)m0*192,
        (const unsigned*)g_woh + (size_t)d0*192, (const unsigned*)g_wol + (size_t)d0*192,
        tid, mw, nw, g, tig, acc);

    int bb = m0 / NTOK, n0 = m0 - bb*NTOK;
    __syncthreads();
    float* fb = (float*)dsm;                 // [128][65]
    #pragma unroll
    for (int mi = 0; mi < 2; mi++)
        #pragma unroll
        for (int rr = 0; rr < 2; rr++) {
            int ml = mw*32 + mi*16 + g + rr*8;
            #pragma unroll
            for (int ni = 0; ni < 4; ni++)
                #pragma unroll
                for (int jj = 0; jj < 2; jj++) {
                    int dl = nw*32 + ni*8 + 2*tig + jj;
                    fb[ml*65 + dl] = acc[mi][ni][rr*2 + jj] + bias[d0 + dl];
                }
        }
    __syncthreads();
    #pragma unroll
    for (int i = tid; i < 64*128; i += 256) {
        int dl = i >> 7, n = i & 127;
        out[((size_t)bb*DIMC + d0 + dl)*NTOK + n0 + n] = fb[n*65 + dl];
    }
}

// ---------------------------------------------------------------------------
extern "C" void kernel_launch(void* const* d_in, const int* in_sizes, int n_in,
                              void* d_out, int out_size) {
    const float* feat  = (const float*)d_in[0];
    const float* gamma = (const float*)d_in[1];
    const float* beta  = (const float*)d_in[2];
    const float* tau   = (const float*)d_in[3];
    const float* w_qkv = (const float*)d_in[4];
    const float* w_out = (const float*)d_in[5];
    const float* b_out = (const float*)d_in[6];
    float* out = (float*)d_out;

    static int smem_set = 0;
    if (!smem_set) {
        cudaFuncSetAttribute(attn_mma, cudaFuncAttributeMaxDynamicSharedMemorySize, 2*ST_SZ);
        cudaFuncSetAttribute(qkv_mma, cudaFuncAttributeMaxDynamicSharedMemorySize, G_SMEM);
        cudaFuncSetAttribute(out_mma, cudaFuncAttributeMaxDynamicSharedMemorySize, G_SMEM);
        smem_set = 1;
    }

    split_w<<<(QKVD*DIMC + 255)/256, 256>>>(w_qkv, w_out);
    ln_kernel<<<dim3(NTOK/64, BATCH), 256>>>(feat, gamma, beta);
    qkv_mma<<<dim3(QKVD/64, BATCH*NTOK/128), 256, G_SMEM>>>();
    attn_mma<<<dim3(NTOK/64, NHEAD, BATCH), 128, 2*ST_SZ>>>(tau);
    out_mma<<<dim3(DIMC/64, BATCH*NTOK/128), 256, G_SMEM>>>(b_out, out);
}